// round 1
// baseline (speedup 1.0000x reference)
#include <cuda_runtime.h>
#include <cuda_bf16.h>

#define B_  2
#define S_  2048
#define D_  1024
#define H_  16
#define DK_ 64
#define M_  (B_*S_)   // 4096

// ---- static device scratch (no allocations allowed) ----
__device__ float g_q[B_*H_*S_*DK_];   // [B,H,S,DK]
__device__ float g_k[B_*H_*S_*DK_];
__device__ float g_v[B_*H_*S_*DK_];
__device__ float g_ctx[M_*D_];        // [B*S, D] merged heads
__device__ float g_pre[M_*D_];        // pre-layernorm (ctx@Wo + residual)

// ============================================================
// GEMM tile body: C[128,128] += A[128,K] * W[K,128], BK=16
// 256 threads (16x16), each 8x8 outputs as 2x2 blocks of 4x4.
// ============================================================
#define GEMM_BODY(Aptr, Wptr, Kdim, Ndim)                                      \
  __shared__ float As[16][128];                                                \
  __shared__ float Bs[16][128];                                                \
  const int tid = threadIdx.x;                                                 \
  const int tx = tid & 15, ty = tid >> 4;                                      \
  const int m0 = blockIdx.y * 128, n0 = blockIdx.x * 128;                      \
  float acc[8][8];                                                             \
  _Pragma("unroll")                                                            \
  for (int i = 0; i < 8; i++)                                                  \
    _Pragma("unroll")                                                          \
    for (int j = 0; j < 8; j++) acc[i][j] = 0.f;                               \
  for (int k0 = 0; k0 < (Kdim); k0 += 16) {                                    \
    _Pragma("unroll")                                                          \
    for (int r = 0; r < 2; r++) {                                              \
      int idx = tid + 256 * r;                                                 \
      int row = idx >> 2, c4 = idx & 3;                                        \
      float4 v = *(const float4*)&(Aptr)[(size_t)(m0 + row) * (Kdim) + k0 + c4 * 4]; \
      As[c4 * 4 + 0][row] = v.x; As[c4 * 4 + 1][row] = v.y;                    \
      As[c4 * 4 + 2][row] = v.z; As[c4 * 4 + 3][row] = v.w;                    \
    }                                                                          \
    _Pragma("unroll")                                                          \
    for (int r = 0; r < 2; r++) {                                              \
      int idx = tid + 256 * r;                                                 \
      int row = idx >> 5, c4 = idx & 31;                                       \
      *(float4*)&Bs[row][c4 * 4] =                                             \
          *(const float4*)&(Wptr)[(size_t)(k0 + row) * (Ndim) + n0 + c4 * 4];  \
    }                                                                          \
    __syncthreads();                                                           \
    _Pragma("unroll")                                                          \
    for (int kk = 0; kk < 16; kk++) {                                          \
      float a[8], bb[8];                                                       \
      *(float4*)&a[0]  = *(const float4*)&As[kk][ty * 4];                      \
      *(float4*)&a[4]  = *(const float4*)&As[kk][64 + ty * 4];                 \
      *(float4*)&bb[0] = *(const float4*)&Bs[kk][tx * 4];                      \
      *(float4*)&bb[4] = *(const float4*)&Bs[kk][64 + tx * 4];                 \
      _Pragma("unroll")                                                        \
      for (int i = 0; i < 8; i++)                                              \
        _Pragma("unroll")                                                      \
        for (int j = 0; j < 8; j++) acc[i][j] += a[i] * bb[j];                 \
    }                                                                          \
    __syncthreads();                                                           \
  }

// ------------------------------------------------------------
// QKV projection: C = X @ W, scattered into [B,H,S,DK]
// grid (8, 32, 3), 256 threads
// ------------------------------------------------------------
__global__ __launch_bounds__(256) void qkv_gemm_kernel(
    const float* __restrict__ xq, const float* __restrict__ xk,
    const float* __restrict__ xv, const float* __restrict__ wq,
    const float* __restrict__ wk, const float* __restrict__ wv) {
  const float* A; const float* W; float* O;
  if (blockIdx.z == 0)      { A = xq; W = wq; O = g_q; }
  else if (blockIdx.z == 1) { A = xk; W = wk; O = g_k; }
  else                      { A = xv; W = wv; O = g_v; }

  GEMM_BODY(A, W, D_, D_)

  _Pragma("unroll")
  for (int i = 0; i < 8; i++) {
    int m = m0 + (i >> 2) * 64 + ty * 4 + (i & 3);
    int b = m >> 11;        // / S_
    int s = m & 2047;
    _Pragma("unroll")
    for (int jn = 0; jn < 2; jn++) {
      int n = n0 + jn * 64 + tx * 4;
      int h = n >> 6;
      int dk = n & 63;
      float4 val = make_float4(acc[i][jn * 4 + 0], acc[i][jn * 4 + 1],
                               acc[i][jn * 4 + 2], acc[i][jn * 4 + 3]);
      *(float4*)&O[(((size_t)b * H_ + h) * S_ + s) * DK_ + dk] = val;
    }
  }
}

// ------------------------------------------------------------
// Output projection: g_pre = g_ctx @ W_O + residual
// grid (8, 32), 256 threads
// ------------------------------------------------------------
__global__ __launch_bounds__(256) void out_gemm_kernel(
    const float* __restrict__ W, const float* __restrict__ resid) {
  const float* A = g_ctx;

  GEMM_BODY(A, W, D_, D_)

  _Pragma("unroll")
  for (int i = 0; i < 8; i++) {
    int m = m0 + (i >> 2) * 64 + ty * 4 + (i & 3);
    _Pragma("unroll")
    for (int jn = 0; jn < 2; jn++) {
      int n = n0 + jn * 64 + tx * 4;
      float4 r = *(const float4*)&resid[(size_t)m * D_ + n];
      float4 val = make_float4(acc[i][jn * 4 + 0] + r.x, acc[i][jn * 4 + 1] + r.y,
                               acc[i][jn * 4 + 2] + r.z, acc[i][jn * 4 + 3] + r.w);
      *(float4*)&g_pre[(size_t)m * D_ + n] = val;
    }
  }
}

// ------------------------------------------------------------
// Flash attention, fp32, 64x64 tiles, online softmax.
// grid (S/64=32, H=16, B=2), 256 threads (16x16).
// Thread (ty,tx): 4 q-rows (ty*4+i). For QK^T it owns k-cols
// {tx+16j}; for PV it owns d-group tx (one float4).
// smem tiles are XOR-swizzled at float4 granularity.
// ------------------------------------------------------------
__global__ __launch_bounds__(256) void attn_kernel(const int* __restrict__ mask) {
  __shared__ float Qs[64 * 64];
  __shared__ float KPs[64 * 64];  // K tile, then reused as P tile
  __shared__ float Vs[64 * 64];

  const int tid = threadIdx.x;
  const int tx = tid & 15, ty = tid >> 4;
  const int qt = blockIdx.x, h = blockIdx.y, b = blockIdx.z;

  const float* __restrict__ Qg = g_q + ((size_t)(b * H_ + h) * S_ + qt * 64) * DK_;
  const float* __restrict__ Kg = g_k + (size_t)(b * H_ + h) * S_ * DK_;
  const float* __restrict__ Vg = g_v + (size_t)(b * H_ + h) * S_ * DK_;
  const int* __restrict__ mrow = mask + (size_t)b * S_ * S_ + (size_t)qt * 64 * S_;

  // load Q tile (swizzled)
#pragma unroll
  for (int r = 0; r < 4; r++) {
    int idx = tid + 256 * r;
    int q = idx >> 4, d4 = idx & 15;
    *(float4*)&Qs[q * 64 + ((d4 ^ (q & 15)) << 2)] =
        *(const float4*)&Qg[q * 64 + d4 * 4];
  }

  float m_run[4] = {-1e30f, -1e30f, -1e30f, -1e30f};
  float l_run[4] = {0.f, 0.f, 0.f, 0.f};
  float4 o[4];
#pragma unroll
  for (int i = 0; i < 4; i++) o[i] = make_float4(0.f, 0.f, 0.f, 0.f);

  for (int kt = 0; kt < S_ / 64; kt++) {
    __syncthreads();  // prior-iter readers of KPs/Vs done
#pragma unroll
    for (int r = 0; r < 4; r++) {
      int idx = tid + 256 * r;
      int k = idx >> 4, d4 = idx & 15;
      int sw = k * 64 + ((d4 ^ (k & 15)) << 2);
      *(float4*)&KPs[sw] = *(const float4*)&Kg[(size_t)(kt * 64 + k) * 64 + d4 * 4];
      *(float4*)&Vs[sw]  = *(const float4*)&Vg[(size_t)(kt * 64 + k) * 64 + d4 * 4];
    }
    __syncthreads();

    // S = Q @ K^T  (4x4 per thread, outer product over d in float4 steps)
    float s[4][4];
#pragma unroll
    for (int i = 0; i < 4; i++)
#pragma unroll
      for (int j = 0; j < 4; j++) s[i][j] = 0.f;

#pragma unroll
    for (int d4 = 0; d4 < 16; d4++) {
      float4 a[4], bb[4];
#pragma unroll
      for (int i = 0; i < 4; i++) {
        int q = ty * 4 + i;
        a[i] = *(const float4*)&Qs[q * 64 + ((d4 ^ (q & 15)) << 2)];
      }
#pragma unroll
      for (int j = 0; j < 4; j++) {
        int k = tx + 16 * j;  // k & 15 == tx
        bb[j] = *(const float4*)&KPs[k * 64 + ((d4 ^ tx) << 2)];
      }
#pragma unroll
      for (int i = 0; i < 4; i++)
#pragma unroll
        for (int j = 0; j < 4; j++)
          s[i][j] += a[i].x * bb[j].x + a[i].y * bb[j].y +
                     a[i].z * bb[j].z + a[i].w * bb[j].w;
    }

    // scale + mask (reference: scale first, masked -> -1e9)
#pragma unroll
    for (int i = 0; i < 4; i++) {
      const int* mr = mrow + (size_t)(ty * 4 + i) * S_ + kt * 64;
#pragma unroll
      for (int j = 0; j < 4; j++) {
        float sv = s[i][j] * 0.125f;
        if (mr[tx + 16 * j]) sv = -1e9f;
        s[i][j] = sv;
      }
    }

    // online softmax (row stats reduced across 16 tx lanes)
#pragma unroll
    for (int i = 0; i < 4; i++) {
      float mx = fmaxf(fmaxf(s[i][0], s[i][1]), fmaxf(s[i][2], s[i][3]));
#pragma unroll
      for (int off = 8; off > 0; off >>= 1)
        mx = fmaxf(mx, __shfl_xor_sync(0xffffffffu, mx, off));
      float mnew = fmaxf(m_run[i], mx);
      float f = __expf(m_run[i] - mnew);
      float ls = 0.f;
#pragma unroll
      for (int j = 0; j < 4; j++) {
        float e = __expf(s[i][j] - mnew);
        s[i][j] = e;
        ls += e;
      }
#pragma unroll
      for (int off = 8; off > 0; off >>= 1)
        ls += __shfl_xor_sync(0xffffffffu, ls, off);
      l_run[i] = l_run[i] * f + ls;
      m_run[i] = mnew;
      o[i].x *= f; o[i].y *= f; o[i].z *= f; o[i].w *= f;
    }

    __syncthreads();  // done reading KPs as K-tile
    // write P (plain [q][k] layout; lanes tx -> consecutive k: conflict-free)
#pragma unroll
    for (int i = 0; i < 4; i++)
#pragma unroll
      for (int j = 0; j < 4; j++)
        KPs[(ty * 4 + i) * 64 + tx + 16 * j] = s[i][j];
    __syncthreads();

    // ctx += P @ V   (thread owns d-group tx, float4 everywhere)
#pragma unroll
    for (int k4 = 0; k4 < 16; k4++) {
      float4 vv[4];
#pragma unroll
      for (int t = 0; t < 4; t++) {
        int k = k4 * 4 + t;
        vv[t] = *(const float4*)&Vs[k * 64 + ((tx ^ (k & 15)) << 2)];
      }
#pragma unroll
      for (int i = 0; i < 4; i++) {
        float4 pp = *(const float4*)&KPs[(ty * 4 + i) * 64 + k4 * 4];
        o[i].x += pp.x * vv[0].x + pp.y * vv[1].x + pp.z * vv[2].x + pp.w * vv[3].x;
        o[i].y += pp.x * vv[0].y + pp.y * vv[1].y + pp.z * vv[2].y + pp.w * vv[3].y;
        o[i].z += pp.x * vv[0].z + pp.y * vv[1].z + pp.z * vv[2].z + pp.w * vv[3].z;
        o[i].w += pp.x * vv[0].w + pp.y * vv[1].w + pp.z * vv[2].w + pp.w * vv[3].w;
      }
    }
  }

  // finalize: divide by l, write merged-head ctx [B*S, D]
#pragma unroll
  for (int i = 0; i < 4; i++) {
    float inv = 1.0f / l_run[i];
    int q = qt * 64 + ty * 4 + i;
    float4 val = make_float4(o[i].x * inv, o[i].y * inv, o[i].z * inv, o[i].w * inv);
    *(float4*)&g_ctx[((size_t)b * S_ + q) * D_ + h * 64 + tx * 4] = val;
  }
}

// ------------------------------------------------------------
// LayerNorm over D=1024, one block per row, 256 threads (4 elems each)
// ------------------------------------------------------------
__global__ __launch_bounds__(256) void ln_kernel(const float* __restrict__ gamma,
                                                 const float* __restrict__ beta,
                                                 float* __restrict__ out) {
  __shared__ float red[8];
  __shared__ float bc;
  const int row = blockIdx.x, tid = threadIdx.x;
  const float* x = g_pre + (size_t)row * D_;
  float4 v = *(const float4*)&x[tid * 4];

  float s = v.x + v.y + v.z + v.w;
#pragma unroll
  for (int off = 16; off > 0; off >>= 1) s += __shfl_xor_sync(0xffffffffu, s, off);
  if ((tid & 31) == 0) red[tid >> 5] = s;
  __syncthreads();
  if (tid == 0) {
    float t = 0.f;
#pragma unroll
    for (int i = 0; i < 8; i++) t += red[i];
    bc = t * (1.0f / D_);
  }
  __syncthreads();
  float mu = bc;

  float dx = v.x - mu, dy = v.y - mu, dz = v.z - mu, dw = v.w - mu;
  float sq = dx * dx + dy * dy + dz * dz + dw * dw;
#pragma unroll
  for (int off = 16; off > 0; off >>= 1) sq += __shfl_xor_sync(0xffffffffu, sq, off);
  __syncthreads();  // everyone has consumed mu / red
  if ((tid & 31) == 0) red[tid >> 5] = sq;
  __syncthreads();
  if (tid == 0) {
    float t = 0.f;
#pragma unroll
    for (int i = 0; i < 8; i++) t += red[i];
    bc = rsqrtf(t * (1.0f / D_) + 1e-5f);
  }
  __syncthreads();
  float inv = bc;

  float4 g = *(const float4*)&gamma[tid * 4];
  float4 be = *(const float4*)&beta[tid * 4];
  float4 o = make_float4(dx * inv * g.x + be.x, dy * inv * g.y + be.y,
                         dz * inv * g.z + be.z, dw * inv * g.w + be.w);
  *(float4*)&out[(size_t)row * D_ + tid * 4] = o;
}

// ------------------------------------------------------------
extern "C" void kernel_launch(void* const* d_in, const int* in_sizes, int n_in,
                              void* d_out, int out_size) {
  const float* xq    = (const float*)d_in[0];
  const float* xk    = (const float*)d_in[1];
  const float* xv    = (const float*)d_in[2];
  const int*   mask  = (const int*)  d_in[3];
  const float* wq    = (const float*)d_in[4];
  const float* wk    = (const float*)d_in[5];
  const float* wv    = (const float*)d_in[6];
  const float* wo    = (const float*)d_in[7];
  const float* gamma = (const float*)d_in[8];
  const float* beta  = (const float*)d_in[9];
  float* out = (float*)d_out;

  qkv_gemm_kernel<<<dim3(8, 32, 3), 256>>>(xq, xk, xv, wq, wk, wv);
  attn_kernel<<<dim3(32, 16, 2), 256>>>(mask);
  out_gemm_kernel<<<dim3(8, 32), 256>>>(wo, xq);
  ln_kernel<<<M_, 256>>>(gamma, beta, out);
}

// round 4
// speedup vs baseline: 1.9991x; 1.9991x over previous
#include <cuda_runtime.h>
#include <cstdint>

#define B_ 2
#define S_ 2048
#define D_ 1024
#define H_ 16
#define DK_ 64
#define M_ (B_*S_)

// ---- static device scratch ----
__device__ float g_q[4194304], g_k[4194304], g_v[4194304];   // tf32 bits, [B,H,S,DK]
__device__ float g_ctx[4194304];                              // tf32 bits, [B*S, D]
__device__ float g_pre[4194304];                              // fp32
__device__ float g_wt[4194304];                               // tf32 bits, W^T x4
__device__ float g_xt[12582912];                              // tf32 bits, xq/xk/xv

// ---- helpers ----
__device__ __forceinline__ uint32_t f2tf(float f) {
  uint32_t u; asm("cvt.rna.tf32.f32 %0, %1;" : "=r"(u) : "f"(f)); return u;
}
__device__ __forceinline__ uint32_t smem_u32(const void* p) {
  uint32_t a;
  asm("{ .reg .u64 t; cvta.to.shared.u64 t, %1; cvt.u32.u64 %0, t; }" : "=r"(a) : "l"(p));
  return a;
}
__device__ __forceinline__ void cp16(uint32_t d, const void* s) {
  asm volatile("cp.async.cg.shared.global [%0], [%1], 16;" :: "r"(d), "l"(s) : "memory");
}
__device__ __forceinline__ void mma8(float* d, const uint32_t* a, const uint32_t* b) {
  asm volatile(
    "mma.sync.aligned.m16n8k8.row.col.f32.tf32.tf32.f32 "
    "{%0,%1,%2,%3}, {%4,%5,%6,%7}, {%8,%9}, {%0,%1,%2,%3};"
    : "+f"(d[0]), "+f"(d[1]), "+f"(d[2]), "+f"(d[3])
    : "r"(a[0]), "r"(a[1]), "r"(a[2]), "r"(a[3]), "r"(b[0]), "r"(b[1]));
}
__device__ __forceinline__ int swz32(int r, int k) {
  return r * 32 + (((((k) >> 2) ^ (r & 7)) << 2) | (k & 3));
}
__device__ __forceinline__ int swz64(int r, int k) {
  return r * 64 + (((((k) >> 2) ^ (r & 15)) << 2) | (k & 3));
}

// ============================================================
// Prepass: convert inputs to tf32 bits
// ============================================================
__global__ __launch_bounds__(256) void cvt_x_kernel(
    const float* __restrict__ xq, const float* __restrict__ xk,
    const float* __restrict__ xv) {
  const float* x = (blockIdx.y == 0) ? xq : (blockIdx.y == 1) ? xk : xv;
  float* o = g_xt + (size_t)blockIdx.y * 4194304;
  size_t i = ((size_t)blockIdx.x * 256 + threadIdx.x) * 4;
  float4 v = *(const float4*)&x[i];
  *(uint4*)&o[i] = make_uint4(f2tf(v.x), f2tf(v.y), f2tf(v.z), f2tf(v.w));
}

// ============================================================
// Weight transpose + tf32 convert: g_wt[z][n][k] = tf32(W_z[k][n])
// ============================================================
__global__ __launch_bounds__(256) void transpose_w_kernel(
    const float* __restrict__ wq, const float* __restrict__ wk,
    const float* __restrict__ wv, const float* __restrict__ wo) {
  __shared__ float t[32][33];
  const int z = blockIdx.z;
  const float* W = (z == 0) ? wq : (z == 1) ? wk : (z == 2) ? wv : wo;
  float* O = g_wt + ((size_t)z << 20);
  const int n0 = blockIdx.x * 32, k0 = blockIdx.y * 32;
  const int tx = threadIdx.x, ty = threadIdx.y;
#pragma unroll
  for (int r = 0; r < 32; r += 8)
    t[ty + r][tx] = W[(size_t)(k0 + ty + r) * 1024 + n0 + tx];
  __syncthreads();
#pragma unroll
  for (int r = 0; r < 32; r += 8)
    O[(size_t)(n0 + ty + r) * 1024 + k0 + tx] = __uint_as_float(f2tf(t[tx][ty + r]));
}

// ============================================================
// tf32 mma.sync GEMM: C[128,128]/CTA, 8 warps x (32m x 64n),
// BK=32, cp.async double-buffered swizzled smem.
// mode 0: QKV (z -> input/weight, scatter tf32 to [B,H,S,DK])
// mode 1: out-proj (A=g_ctx, +resid -> g_pre fp32)
// ============================================================
__global__ __launch_bounds__(256) void gemm_tc_kernel(const float* __restrict__ resid,
                                                      int mode) {
  extern __shared__ uint32_t dsm[];  // 2 stages x (A 4096 + B 4096) words
  const int tid = threadIdx.x, lane = tid & 31, wid = tid >> 5;
  const int wm = wid & 3, wn = wid >> 2;
  const int z = blockIdx.z;
  const float* A = (mode == 0) ? (g_xt + (size_t)z * 4194304) : g_ctx;
  const float* Wt = g_wt + ((size_t)(mode == 0 ? z : 3) << 20);
  const int m0 = blockIdx.y * 128, n0 = blockIdx.x * 128;
  const uint32_t sbase = smem_u32(dsm);

  float acc[2][8][4];
#pragma unroll
  for (int i = 0; i < 2; i++)
#pragma unroll
    for (int j = 0; j < 8; j++)
#pragma unroll
      for (int q = 0; q < 4; q++) acc[i][j][q] = 0.f;

#define GEMM_ISSUE(st, kc) do {                                                \
    uint32_t _b = sbase + (st) * 32768;                                        \
    _Pragma("unroll")                                                          \
    for (int t = 0; t < 4; ++t) {                                              \
      int idx = tid + t * 256;                                                 \
      int row = idx >> 3, g = idx & 7;                                         \
      uint32_t off = (uint32_t)(row * 32 + ((g ^ (row & 7)) << 2)) * 4;        \
      cp16(_b + off, A + (size_t)(m0 + row) * 1024 + (kc) + g * 4);            \
      cp16(_b + 16384 + off, Wt + (size_t)(n0 + row) * 1024 + (kc) + g * 4);   \
    }                                                                          \
    asm volatile("cp.async.commit_group;" ::: "memory");                       \
  } while (0)

  GEMM_ISSUE(0, 0);

  for (int kt = 0; kt < 32; ++kt) {
    const int s = kt & 1;
    if (kt < 31) {
      GEMM_ISSUE(s ^ 1, (kt + 1) * 32);
      asm volatile("cp.async.wait_group 1;" ::: "memory");
    } else {
      asm volatile("cp.async.wait_group 0;" ::: "memory");
    }
    __syncthreads();
    const uint32_t* As = dsm + s * 8192;
    const uint32_t* Bs = As + 4096;
#pragma unroll
    for (int ks = 0; ks < 4; ++ks) {
      const int k0 = ks * 8 + (lane & 3);
      uint32_t af[2][4];
#pragma unroll
      for (int tm = 0; tm < 2; ++tm) {
        int m = wm * 32 + tm * 16 + (lane >> 2);
        af[tm][0] = As[swz32(m, k0)];
        af[tm][1] = As[swz32(m + 8, k0)];
        af[tm][2] = As[swz32(m, k0 + 4)];
        af[tm][3] = As[swz32(m + 8, k0 + 4)];
      }
#pragma unroll
      for (int tn = 0; tn < 8; ++tn) {
        int n = wn * 64 + tn * 8 + (lane >> 2);
        uint32_t bf[2] = {Bs[swz32(n, k0)], Bs[swz32(n, k0 + 4)]};
        mma8(acc[0][tn], af[0], bf);
        mma8(acc[1][tn], af[1], bf);
      }
    }
    __syncthreads();
  }

#pragma unroll
  for (int tm = 0; tm < 2; ++tm) {
#pragma unroll
    for (int tn = 0; tn < 8; ++tn) {
      const int m = m0 + wm * 32 + tm * 16 + (lane >> 2);
      const int n = n0 + wn * 64 + tn * 8 + 2 * (lane & 3);
      float* c = acc[tm][tn];
      if (mode == 0) {
        float* O = (z == 0) ? g_q : (z == 1) ? g_k : g_v;
        const int b = m >> 11, sq = m & 2047, h = n >> 6, dk = n & 63;
        *(float2*)&O[(((size_t)b * H_ + h) * S_ + sq) * 64 + dk] =
            make_float2(__uint_as_float(f2tf(c[0])), __uint_as_float(f2tf(c[1])));
        *(float2*)&O[(((size_t)b * H_ + h) * S_ + sq + 8) * 64 + dk] =
            make_float2(__uint_as_float(f2tf(c[2])), __uint_as_float(f2tf(c[3])));
      } else {
        float2 r0 = *(const float2*)&resid[(size_t)m * 1024 + n];
        float2 r1 = *(const float2*)&resid[(size_t)(m + 8) * 1024 + n];
        *(float2*)&g_pre[(size_t)m * 1024 + n] = make_float2(c[0] + r0.x, c[1] + r0.y);
        *(float2*)&g_pre[(size_t)(m + 8) * 1024 + n] = make_float2(c[2] + r1.x, c[3] + r1.y);
      }
    }
  }
}

// ============================================================
// Flash attention on tf32 mma.sync. 64 q-rows/CTA, 8 warps.
// QK^T: warp = 16q x 32keys. PV: warp = 16q x 32dk.
// smem: QPs 4096w + Ks 4096w + Vs 4096w + smax 128f + ssum 128f
//     = 50176 bytes
// ============================================================
#define ATT_SMEM 50176
__global__ __launch_bounds__(256) void attn_kernel(const int* __restrict__ mask) {
  extern __shared__ uint32_t sm[];
  uint32_t* QPs = sm;            // 4096 words: Q tile, then P tile
  uint32_t* Ks = sm + 4096;
  uint32_t* Vs = sm + 8192;
  float* smax = (float*)(sm + 12288);  // [2][64]
  float* ssum = smax + 128;            // [2][64]

  const int tid = threadIdx.x, lane = tid & 31, wid = tid >> 5;
  const int wm = wid & 3, wn = wid >> 2;
  const int qt = blockIdx.x, h = blockIdx.y, b = blockIdx.z;
  const float* Qg = g_q + ((size_t)(b * H_ + h) * S_ + qt * 64) * 64;
  const float* Kg = g_k + (size_t)(b * H_ + h) * S_ * 64;
  const float* Vg = g_v + (size_t)(b * H_ + h) * S_ * 64;
  const int* mkb = mask + (size_t)b * S_ * S_;

  // stage Q (already tf32 bits)
#pragma unroll
  for (int t = 0; t < 4; ++t) {
    int idx = tid + t * 256;
    int row = idx >> 4, g = idx & 15;
    uint4 v = *(const uint4*)&Qg[row * 64 + g * 4];
    *(uint4*)&QPs[row * 64 + ((g ^ (row & 15)) << 2)] = v;
  }
  __syncthreads();

  const int r0 = wm * 16 + (lane >> 2);
  uint32_t qa[8][4];
#pragma unroll
  for (int ks = 0; ks < 8; ++ks) {
    int k0 = ks * 8 + (lane & 3);
    qa[ks][0] = QPs[swz64(r0, k0)];
    qa[ks][1] = QPs[swz64(r0 + 8, k0)];
    qa[ks][2] = QPs[swz64(r0, k0 + 4)];
    qa[ks][3] = QPs[swz64(r0 + 8, k0 + 4)];
  }

  float o[4][4];
#pragma unroll
  for (int i = 0; i < 4; i++)
#pragma unroll
    for (int j = 0; j < 4; j++) o[i][j] = 0.f;
  float m0r = -1e30f, m1r = -1e30f, l0r = 0.f, l1r = 0.f;
  const int qg0 = qt * 64 + r0;

  for (int kt = 0; kt < 32; ++kt) {
    // prefetch mask (int2: two consecutive cols)
    int2 mk0[4], mk1[4];
#pragma unroll
    for (int tn = 0; tn < 4; ++tn) {
      int col = kt * 64 + wn * 32 + tn * 8 + 2 * (lane & 3);
      mk0[tn] = *(const int2*)&mkb[(size_t)qg0 * S_ + col];
      mk1[tn] = *(const int2*)&mkb[(size_t)(qg0 + 8) * S_ + col];
    }
    __syncthreads();  // prev PV done reading Vs/QPs
#pragma unroll
    for (int t = 0; t < 4; ++t) {
      int idx = tid + t * 256;
      int row = idx >> 4, g = idx & 15;
      uint4 kv = *(const uint4*)&Kg[(size_t)(kt * 64 + row) * 64 + g * 4];
      uint4 vv = *(const uint4*)&Vg[(size_t)(kt * 64 + row) * 64 + g * 4];
      int off = row * 64 + ((g ^ (row & 15)) << 2);
      *(uint4*)&Ks[off] = kv;
      *(uint4*)&Vs[off] = vv;
    }
    __syncthreads();

    // S = Q K^T
    float s[4][4];
#pragma unroll
    for (int i = 0; i < 4; i++)
#pragma unroll
      for (int j = 0; j < 4; j++) s[i][j] = 0.f;
#pragma unroll
    for (int ks = 0; ks < 8; ++ks) {
      int k0 = ks * 8 + (lane & 3);
#pragma unroll
      for (int tn = 0; tn < 4; ++tn) {
        int n = wn * 32 + tn * 8 + (lane >> 2);
        uint32_t bf[2] = {Ks[swz64(n, k0)], Ks[swz64(n, k0 + 4)]};
        mma8(s[tn], qa[ks], bf);
      }
    }

    // scale + mask
#pragma unroll
    for (int tn = 0; tn < 4; ++tn) {
      s[tn][0] = mk0[tn].x ? -1e9f : s[tn][0] * 0.125f;
      s[tn][1] = mk0[tn].y ? -1e9f : s[tn][1] * 0.125f;
      s[tn][2] = mk1[tn].x ? -1e9f : s[tn][2] * 0.125f;
      s[tn][3] = mk1[tn].y ? -1e9f : s[tn][3] * 0.125f;
    }

    // row max (quad reduce + cross-warp_n via smem)
    float mx0 = -1e30f, mx1 = -1e30f;
#pragma unroll
    for (int tn = 0; tn < 4; ++tn) {
      mx0 = fmaxf(mx0, fmaxf(s[tn][0], s[tn][1]));
      mx1 = fmaxf(mx1, fmaxf(s[tn][2], s[tn][3]));
    }
    mx0 = fmaxf(mx0, __shfl_xor_sync(0xffffffffu, mx0, 1));
    mx0 = fmaxf(mx0, __shfl_xor_sync(0xffffffffu, mx0, 2));
    mx1 = fmaxf(mx1, __shfl_xor_sync(0xffffffffu, mx1, 1));
    mx1 = fmaxf(mx1, __shfl_xor_sync(0xffffffffu, mx1, 2));
    if ((lane & 3) == 0) {
      smax[wn * 64 + r0] = mx0;
      smax[wn * 64 + r0 + 8] = mx1;
    }
    __syncthreads();
    float mn0 = fmaxf(m0r, fmaxf(smax[r0], smax[64 + r0]));
    float mn1 = fmaxf(m1r, fmaxf(smax[r0 + 8], smax[64 + r0 + 8]));
    float f0 = __expf(m0r - mn0), f1 = __expf(m1r - mn1);
    m0r = mn0; m1r = mn1;

    float ls0 = 0.f, ls1 = 0.f;
#pragma unroll
    for (int tn = 0; tn < 4; ++tn) {
      s[tn][0] = __expf(s[tn][0] - mn0); ls0 += s[tn][0];
      s[tn][1] = __expf(s[tn][1] - mn0); ls0 += s[tn][1];
      s[tn][2] = __expf(s[tn][2] - mn1); ls1 += s[tn][2];
      s[tn][3] = __expf(s[tn][3] - mn1); ls1 += s[tn][3];
    }
    ls0 += __shfl_xor_sync(0xffffffffu, ls0, 1);
    ls0 += __shfl_xor_sync(0xffffffffu, ls0, 2);
    ls1 += __shfl_xor_sync(0xffffffffu, ls1, 1);
    ls1 += __shfl_xor_sync(0xffffffffu, ls1, 2);
    if ((lane & 3) == 0) {
      ssum[wn * 64 + r0] = ls0;
      ssum[wn * 64 + r0 + 8] = ls1;
    }
    __syncthreads();
    l0r = l0r * f0 + ssum[r0] + ssum[64 + r0];
    l1r = l1r * f1 + ssum[r0 + 8] + ssum[64 + r0 + 8];
#pragma unroll
    for (int tn = 0; tn < 4; ++tn) {
      o[tn][0] *= f0; o[tn][1] *= f0; o[tn][2] *= f1; o[tn][3] *= f1;
    }

    // write P (tf32)
#pragma unroll
    for (int tn = 0; tn < 4; ++tn) {
      int c = wn * 32 + tn * 8 + 2 * (lane & 3);
      int p0 = swz64(r0, c), p1 = swz64(r0 + 8, c);
      QPs[p0] = f2tf(s[tn][0]); QPs[p0 + 1] = f2tf(s[tn][1]);
      QPs[p1] = f2tf(s[tn][2]); QPs[p1 + 1] = f2tf(s[tn][3]);
    }
    __syncthreads();

    // ctx += P V
#pragma unroll
    for (int ks = 0; ks < 8; ++ks) {
      int k0 = ks * 8 + (lane & 3);
      uint32_t pa[4] = {QPs[swz64(r0, k0)], QPs[swz64(r0 + 8, k0)],
                        QPs[swz64(r0, k0 + 4)], QPs[swz64(r0 + 8, k0 + 4)]};
#pragma unroll
      for (int tn = 0; tn < 4; ++tn) {
        int nd = wn * 32 + tn * 8 + (lane >> 2);
        uint32_t vf[2] = {Vs[swz64(k0, nd)], Vs[swz64(k0 + 4, nd)]};
        mma8(o[tn], pa, vf);
      }
    }
  }

  // epilogue -> g_ctx (tf32 bits, merged heads)
  const float i0 = 1.f / l0r, i1 = 1.f / l1r;
#pragma unroll
  for (int tn = 0; tn < 4; ++tn) {
    int dk = wn * 32 + tn * 8 + 2 * (lane & 3);
    size_t base = ((size_t)b * S_ + qt * 64 + r0) * 1024 + h * 64 + dk;
    *(float2*)&g_ctx[base] = make_float2(__uint_as_float(f2tf(o[tn][0] * i0)),
                                         __uint_as_float(f2tf(o[tn][1] * i0)));
    *(float2*)&g_ctx[base + 8 * 1024] = make_float2(__uint_as_float(f2tf(o[tn][2] * i1)),
                                                    __uint_as_float(f2tf(o[tn][3] * i1)));
  }
}

// ------------------------------------------------------------
// LayerNorm over D=1024
// ------------------------------------------------------------
__global__ __launch_bounds__(256) void ln_kernel(const float* __restrict__ gamma,
                                                 const float* __restrict__ beta,
                                                 float* __restrict__ out) {
  __shared__ float red[8];
  __shared__ float bc;
  const int row = blockIdx.x, tid = threadIdx.x;
  const float* x = g_pre + (size_t)row * D_;
  float4 v = *(const float4*)&x[tid * 4];

  float s = v.x + v.y + v.z + v.w;
#pragma unroll
  for (int off = 16; off > 0; off >>= 1) s += __shfl_xor_sync(0xffffffffu, s, off);
  if ((tid & 31) == 0) red[tid >> 5] = s;
  __syncthreads();
  if (tid == 0) {
    float t = 0.f;
#pragma unroll
    for (int i = 0; i < 8; i++) t += red[i];
    bc = t * (1.0f / D_);
  }
  __syncthreads();
  float mu = bc;

  float dx = v.x - mu, dy = v.y - mu, dz = v.z - mu, dw = v.w - mu;
  float sq = dx * dx + dy * dy + dz * dz + dw * dw;
#pragma unroll
  for (int off = 16; off > 0; off >>= 1) sq += __shfl_xor_sync(0xffffffffu, sq, off);
  __syncthreads();
  if ((tid & 31) == 0) red[tid >> 5] = sq;
  __syncthreads();
  if (tid == 0) {
    float t = 0.f;
#pragma unroll
    for (int i = 0; i < 8; i++) t += red[i];
    bc = rsqrtf(t * (1.0f / D_) + 1e-5f);
  }
  __syncthreads();
  float inv = bc;

  float4 g = *(const float4*)&gamma[tid * 4];
  float4 be = *(const float4*)&beta[tid * 4];
  *(float4*)&out[(size_t)row * D_ + tid * 4] =
      make_float4(dx * inv * g.x + be.x, dy * inv * g.y + be.y,
                  dz * inv * g.z + be.z, dw * inv * g.w + be.w);
}

// ------------------------------------------------------------
extern "C" void kernel_launch(void* const* d_in, const int* in_sizes, int n_in,
                              void* d_out, int out_size) {
  const float* xq    = (const float*)d_in[0];
  const float* xk    = (const float*)d_in[1];
  const float* xv    = (const float*)d_in[2];
  const int*   mask  = (const int*)  d_in[3];
  const float* wq    = (const float*)d_in[4];
  const float* wk    = (const float*)d_in[5];
  const float* wv    = (const float*)d_in[6];
  const float* wo    = (const float*)d_in[7];
  const float* gamma = (const float*)d_in[8];
  const float* beta  = (const float*)d_in[9];
  float* out = (float*)d_out;

  cudaFuncSetAttribute(gemm_tc_kernel, cudaFuncAttributeMaxDynamicSharedMemorySize, 65536);
  cudaFuncSetAttribute(attn_kernel, cudaFuncAttributeMaxDynamicSharedMemorySize, ATT_SMEM);

  cvt_x_kernel<<<dim3(4096, 3), 256>>>(xq, xk, xv);
  transpose_w_kernel<<<dim3(32, 32, 4), dim3(32, 8)>>>(wq, wk, wv, wo);
  gemm_tc_kernel<<<dim3(8, 32, 3), 256, 65536>>>(nullptr, 0);
  attn_kernel<<<dim3(32, 16, 2), 256, ATT_SMEM>>>(mask);
  gemm_tc_kernel<<<dim3(8, 32, 1), 256, 65536>>>(xq, 1);
  ln_kernel<<<M_, 256>>>(gamma, beta, out);
}

// round 5
// speedup vs baseline: 2.5516x; 1.2764x over previous
#include <cuda_runtime.h>
#include <cstdint>

#define B_ 2
#define S_ 2048
#define D_ 1024
#define H_ 16
#define DK_ 64
#define M_ (B_*S_)

// ---- static device scratch ----
__device__ float g_q[4194304], g_k[4194304], g_v[4194304];   // tf32 bits, [B,H,S,DK]
__device__ float g_ctx[4194304];                              // tf32 bits, [B*S, D]
__device__ float g_pre[4194304];                              // fp32
__device__ float g_wt[4194304];                               // tf32 bits, W^T x4
__device__ float g_xt[12582912];                              // tf32 bits, xq/xk/xv

// ---- helpers ----
__device__ __forceinline__ uint32_t f2tf(float f) {
  uint32_t u; asm("cvt.rna.tf32.f32 %0, %1;" : "=r"(u) : "f"(f)); return u;
}
__device__ __forceinline__ uint32_t smem_u32(const void* p) {
  uint32_t a;
  asm("{ .reg .u64 t; cvta.to.shared.u64 t, %1; cvt.u32.u64 %0, t; }" : "=r"(a) : "l"(p));
  return a;
}
__device__ __forceinline__ void cp16(uint32_t d, const void* s) {
  asm volatile("cp.async.cg.shared.global [%0], [%1], 16;" :: "r"(d), "l"(s) : "memory");
}
__device__ __forceinline__ void mma8(float* d, const uint32_t* a, const uint32_t* b) {
  asm volatile(
    "mma.sync.aligned.m16n8k8.row.col.f32.tf32.tf32.f32 "
    "{%0,%1,%2,%3}, {%4,%5,%6,%7}, {%8,%9}, {%0,%1,%2,%3};"
    : "+f"(d[0]), "+f"(d[1]), "+f"(d[2]), "+f"(d[3])
    : "r"(a[0]), "r"(a[1]), "r"(a[2]), "r"(a[3]), "r"(b[0]), "r"(b[1]));
}
__device__ __forceinline__ int swz32(int r, int k) {
  return r * 32 + (((((k) >> 2) ^ (r & 7)) << 2) | (k & 3));
}
__device__ __forceinline__ int swz64(int r, int k) {
  return r * 64 + (((((k) >> 2) ^ (r & 15)) << 2) | (k & 3));
}

// ============================================================
// Prepass: convert inputs to tf32 bits
// ============================================================
__global__ __launch_bounds__(256) void cvt_x_kernel(
    const float* __restrict__ xq, const float* __restrict__ xk,
    const float* __restrict__ xv) {
  const float* x = (blockIdx.y == 0) ? xq : (blockIdx.y == 1) ? xk : xv;
  float* o = g_xt + (size_t)blockIdx.y * 4194304;
  size_t i = ((size_t)blockIdx.x * 256 + threadIdx.x) * 4;
  float4 v = *(const float4*)&x[i];
  *(uint4*)&o[i] = make_uint4(f2tf(v.x), f2tf(v.y), f2tf(v.z), f2tf(v.w));
}

// ============================================================
// Weight transpose + tf32 convert: g_wt[z][n][k] = tf32(W_z[k][n])
// ============================================================
__global__ __launch_bounds__(256) void transpose_w_kernel(
    const float* __restrict__ wq, const float* __restrict__ wk,
    const float* __restrict__ wv, const float* __restrict__ wo) {
  __shared__ float t[32][33];
  const int z = blockIdx.z;
  const float* W = (z == 0) ? wq : (z == 1) ? wk : (z == 2) ? wv : wo;
  float* O = g_wt + ((size_t)z << 20);
  const int n0 = blockIdx.x * 32, k0 = blockIdx.y * 32;
  const int tx = threadIdx.x, ty = threadIdx.y;
#pragma unroll
  for (int r = 0; r < 32; r += 8)
    t[ty + r][tx] = W[(size_t)(k0 + ty + r) * 1024 + n0 + tx];
  __syncthreads();
#pragma unroll
  for (int r = 0; r < 32; r += 8)
    O[(size_t)(n0 + ty + r) * 1024 + k0 + tx] = __uint_as_float(f2tf(t[tx][ty + r]));
}

// ============================================================
// tf32 mma.sync GEMM (unchanged from R4 passing version)
// ============================================================
__global__ __launch_bounds__(256) void gemm_tc_kernel(const float* __restrict__ resid,
                                                      int mode) {
  extern __shared__ uint32_t dsm[];
  const int tid = threadIdx.x, lane = tid & 31, wid = tid >> 5;
  const int wm = wid & 3, wn = wid >> 2;
  const int z = blockIdx.z;
  const float* A = (mode == 0) ? (g_xt + (size_t)z * 4194304) : g_ctx;
  const float* Wt = g_wt + ((size_t)(mode == 0 ? z : 3) << 20);
  const int m0 = blockIdx.y * 128, n0 = blockIdx.x * 128;
  const uint32_t sbase = smem_u32(dsm);

  float acc[2][8][4];
#pragma unroll
  for (int i = 0; i < 2; i++)
#pragma unroll
    for (int j = 0; j < 8; j++)
#pragma unroll
      for (int q = 0; q < 4; q++) acc[i][j][q] = 0.f;

#define GEMM_ISSUE(st, kc) do {                                                \
    uint32_t _b = sbase + (st) * 32768;                                        \
    _Pragma("unroll")                                                          \
    for (int t = 0; t < 4; ++t) {                                              \
      int idx = tid + t * 256;                                                 \
      int row = idx >> 3, g = idx & 7;                                         \
      uint32_t off = (uint32_t)(row * 32 + ((g ^ (row & 7)) << 2)) * 4;        \
      cp16(_b + off, A + (size_t)(m0 + row) * 1024 + (kc) + g * 4);            \
      cp16(_b + 16384 + off, Wt + (size_t)(n0 + row) * 1024 + (kc) + g * 4);   \
    }                                                                          \
    asm volatile("cp.async.commit_group;" ::: "memory");                       \
  } while (0)

  GEMM_ISSUE(0, 0);

  for (int kt = 0; kt < 32; ++kt) {
    const int s = kt & 1;
    if (kt < 31) {
      GEMM_ISSUE(s ^ 1, (kt + 1) * 32);
      asm volatile("cp.async.wait_group 1;" ::: "memory");
    } else {
      asm volatile("cp.async.wait_group 0;" ::: "memory");
    }
    __syncthreads();
    const uint32_t* As = dsm + s * 8192;
    const uint32_t* Bs = As + 4096;
#pragma unroll
    for (int ks = 0; ks < 4; ++ks) {
      const int k0 = ks * 8 + (lane & 3);
      uint32_t af[2][4];
#pragma unroll
      for (int tm = 0; tm < 2; ++tm) {
        int m = wm * 32 + tm * 16 + (lane >> 2);
        af[tm][0] = As[swz32(m, k0)];
        af[tm][1] = As[swz32(m + 8, k0)];
        af[tm][2] = As[swz32(m, k0 + 4)];
        af[tm][3] = As[swz32(m + 8, k0 + 4)];
      }
#pragma unroll
      for (int tn = 0; tn < 8; ++tn) {
        int n = wn * 64 + tn * 8 + (lane >> 2);
        uint32_t bf[2] = {Bs[swz32(n, k0)], Bs[swz32(n, k0 + 4)]};
        mma8(acc[0][tn], af[0], bf);
        mma8(acc[1][tn], af[1], bf);
      }
    }
    __syncthreads();
  }

#pragma unroll
  for (int tm = 0; tm < 2; ++tm) {
#pragma unroll
    for (int tn = 0; tn < 8; ++tn) {
      const int m = m0 + wm * 32 + tm * 16 + (lane >> 2);
      const int n = n0 + wn * 64 + tn * 8 + 2 * (lane & 3);
      float* c = acc[tm][tn];
      if (mode == 0) {
        float* O = (z == 0) ? g_q : (z == 1) ? g_k : g_v;
        const int b = m >> 11, sq = m & 2047, h = n >> 6, dk = n & 63;
        *(float2*)&O[(((size_t)b * H_ + h) * S_ + sq) * 64 + dk] =
            make_float2(__uint_as_float(f2tf(c[0])), __uint_as_float(f2tf(c[1])));
        *(float2*)&O[(((size_t)b * H_ + h) * S_ + sq + 8) * 64 + dk] =
            make_float2(__uint_as_float(f2tf(c[2])), __uint_as_float(f2tf(c[3])));
      } else {
        float2 r0 = *(const float2*)&resid[(size_t)m * 1024 + n];
        float2 r1 = *(const float2*)&resid[(size_t)(m + 8) * 1024 + n];
        *(float2*)&g_pre[(size_t)m * 1024 + n] = make_float2(c[0] + r0.x, c[1] + r0.y);
        *(float2*)&g_pre[(size_t)(m + 8) * 1024 + n] = make_float2(c[2] + r1.x, c[3] + r1.y);
      }
    }
  }
}

// ============================================================
// Flash attention v2: 128 threads, 4 warps, warp = 16q x 64keys.
// Warp-local softmax (quad shuffles). P stays in registers:
// C-fragments -> A-fragments via intra-quad shuffles.
// smem: Q 4096w + K 4096w + V 4096w = 49152 B.
// ============================================================
#define ATT_SMEM 49152
__global__ __launch_bounds__(128, 3) void attn_kernel(const int* __restrict__ mask) {
  extern __shared__ uint32_t sm[];
  uint32_t* Qs = sm;
  uint32_t* Ks = sm + 4096;
  uint32_t* Vs = sm + 8192;
  const uint32_t ksb = smem_u32(Ks), vsb = smem_u32(Vs);

  const int tid = threadIdx.x, lane = tid & 31, w = tid >> 5;
  const int qt = blockIdx.x, h = blockIdx.y, b = blockIdx.z;
  const float* Qg = g_q + ((size_t)(b * H_ + h) * S_ + qt * 64) * 64;
  const float* Kg = g_k + (size_t)(b * H_ + h) * S_ * 64;
  const float* Vg = g_v + (size_t)(b * H_ + h) * S_ * 64;
  const int* mkb = mask + (size_t)b * S_ * S_;

  // stage Q (tf32 bits), swizzled
#pragma unroll
  for (int t = 0; t < 8; ++t) {
    int idx = tid + t * 128;
    int row = idx >> 4, g = idx & 15;
    uint4 v = *(const uint4*)&Qg[row * 64 + g * 4];
    *(uint4*)&Qs[row * 64 + ((g ^ (row & 15)) << 2)] = v;
  }
  __syncthreads();

  const int qr = lane >> 2;            // quad row 0..7
  const int qq = lane & 3;             // quad col 0..3
  const int r0 = w * 16 + qr;          // local q row (and +8)
  uint32_t qa[8][4];
#pragma unroll
  for (int ks = 0; ks < 8; ++ks) {
    int k0 = ks * 8 + qq;
    qa[ks][0] = Qs[swz64(r0, k0)];
    qa[ks][1] = Qs[swz64(r0 + 8, k0)];
    qa[ks][2] = Qs[swz64(r0, k0 + 4)];
    qa[ks][3] = Qs[swz64(r0 + 8, k0 + 4)];
  }
  __syncthreads();  // Qs reads done (Qs not reused, but keep staging clean)

  float o[8][4];
#pragma unroll
  for (int i = 0; i < 8; i++)
#pragma unroll
    for (int j = 0; j < 4; j++) o[i][j] = 0.f;
  float m0r = -1e30f, m1r = -1e30f, l0r = 0.f, l1r = 0.f;
  const int qg0 = qt * 64 + r0;
  const int srcA = (lane & ~3) | (qq >> 1);  // shuffle src for cols q
  const int srcB = srcA + 2;                 // shuffle src for cols q+4

  for (int kt = 0; kt < 32; ++kt) {
    __syncthreads();  // prev iteration's K/V reads done
    // stage K/V via cp.async (64x64 tf32 words each)
#pragma unroll
    for (int t = 0; t < 8; ++t) {
      int idx = tid + t * 128;
      int row = idx >> 4, g = idx & 15;
      uint32_t off = (uint32_t)(row * 64 + ((g ^ (row & 15)) << 2)) * 4;
      const size_t gof = (size_t)(kt * 64 + row) * 64 + g * 4;
      cp16(ksb + off, Kg + gof);
      cp16(vsb + off, Vg + gof);
    }
    asm volatile("cp.async.commit_group;" ::: "memory");
    asm volatile("cp.async.wait_group 0;" ::: "memory");
    __syncthreads();

    // S = Q K^T : warp tile 16q x 64keys
    float s[8][4];
#pragma unroll
    for (int i = 0; i < 8; i++)
#pragma unroll
      for (int j = 0; j < 4; j++) s[i][j] = 0.f;
#pragma unroll
    for (int ks = 0; ks < 8; ++ks) {
      int k0 = ks * 8 + qq;
#pragma unroll
      for (int tn = 0; tn < 8; ++tn) {
        int n = tn * 8 + qr;
        uint32_t bf[2] = {Ks[swz64(n, k0)], Ks[swz64(n, k0 + 4)]};
        mma8(s[tn], qa[ks], bf);
      }
    }

    // scale + mask (loads issued back-to-back, consumed in order)
#pragma unroll
    for (int tn = 0; tn < 8; ++tn) {
      int col = kt * 64 + tn * 8 + 2 * qq;
      int2 mk0 = *(const int2*)&mkb[(size_t)qg0 * S_ + col];
      int2 mk1 = *(const int2*)&mkb[(size_t)(qg0 + 8) * S_ + col];
      s[tn][0] = mk0.x ? -1e9f : s[tn][0] * 0.125f;
      s[tn][1] = mk0.y ? -1e9f : s[tn][1] * 0.125f;
      s[tn][2] = mk1.x ? -1e9f : s[tn][2] * 0.125f;
      s[tn][3] = mk1.y ? -1e9f : s[tn][3] * 0.125f;
    }

    // warp-local softmax (rows r0 / r0+8 live in one quad)
    float mx0 = -1e30f, mx1 = -1e30f;
#pragma unroll
    for (int tn = 0; tn < 8; ++tn) {
      mx0 = fmaxf(mx0, fmaxf(s[tn][0], s[tn][1]));
      mx1 = fmaxf(mx1, fmaxf(s[tn][2], s[tn][3]));
    }
    mx0 = fmaxf(mx0, __shfl_xor_sync(0xffffffffu, mx0, 1));
    mx0 = fmaxf(mx0, __shfl_xor_sync(0xffffffffu, mx0, 2));
    mx1 = fmaxf(mx1, __shfl_xor_sync(0xffffffffu, mx1, 1));
    mx1 = fmaxf(mx1, __shfl_xor_sync(0xffffffffu, mx1, 2));
    float mn0 = fmaxf(m0r, mx0), mn1 = fmaxf(m1r, mx1);
    float f0 = __expf(m0r - mn0), f1 = __expf(m1r - mn1);
    m0r = mn0; m1r = mn1;

    float ls0 = 0.f, ls1 = 0.f;
#pragma unroll
    for (int tn = 0; tn < 8; ++tn) {
      s[tn][0] = __expf(s[tn][0] - mn0); ls0 += s[tn][0];
      s[tn][1] = __expf(s[tn][1] - mn0); ls0 += s[tn][1];
      s[tn][2] = __expf(s[tn][2] - mn1); ls1 += s[tn][2];
      s[tn][3] = __expf(s[tn][3] - mn1); ls1 += s[tn][3];
    }
    ls0 += __shfl_xor_sync(0xffffffffu, ls0, 1);
    ls0 += __shfl_xor_sync(0xffffffffu, ls0, 2);
    ls1 += __shfl_xor_sync(0xffffffffu, ls1, 1);
    ls1 += __shfl_xor_sync(0xffffffffu, ls1, 2);
    l0r = l0r * f0 + ls0;
    l1r = l1r * f1 + ls1;
#pragma unroll
    for (int dt = 0; dt < 8; ++dt) {
      o[dt][0] *= f0; o[dt][1] *= f0; o[dt][2] *= f1; o[dt][3] *= f1;
    }

    // P C-frag -> A-frag in registers (intra-quad shuffles), then PV
#pragma unroll
    for (int ks = 0; ks < 8; ++ks) {
      float t00 = __shfl_sync(0xffffffffu, s[ks][0], srcA);
      float t01 = __shfl_sync(0xffffffffu, s[ks][1], srcA);
      float t02 = __shfl_sync(0xffffffffu, s[ks][0], srcB);
      float t03 = __shfl_sync(0xffffffffu, s[ks][1], srcB);
      float t10 = __shfl_sync(0xffffffffu, s[ks][2], srcA);
      float t11 = __shfl_sync(0xffffffffu, s[ks][3], srcA);
      float t12 = __shfl_sync(0xffffffffu, s[ks][2], srcB);
      float t13 = __shfl_sync(0xffffffffu, s[ks][3], srcB);
      uint32_t pa[4];
      pa[0] = f2tf((qq & 1) ? t01 : t00);  // (r0,   ks*8+qq)
      pa[1] = f2tf((qq & 1) ? t11 : t10);  // (r0+8, ks*8+qq)
      pa[2] = f2tf((qq & 1) ? t03 : t02);  // (r0,   ks*8+qq+4)
      pa[3] = f2tf((qq & 1) ? t13 : t12);  // (r0+8, ks*8+qq+4)
      int k0 = ks * 8 + qq;
#pragma unroll
      for (int dt = 0; dt < 8; ++dt) {
        int nd = dt * 8 + qr;
        uint32_t vf[2] = {Vs[swz64(k0, nd)], Vs[swz64(k0 + 4, nd)]};
        mma8(o[dt], pa, vf);
      }
    }
  }

  // epilogue -> g_ctx (tf32 bits, merged heads)
  const float i0 = 1.f / l0r, i1 = 1.f / l1r;
#pragma unroll
  for (int dt = 0; dt < 8; ++dt) {
    int dk = dt * 8 + 2 * qq;
    size_t base = ((size_t)b * S_ + qt * 64 + r0) * 1024 + h * 64 + dk;
    *(float2*)&g_ctx[base] = make_float2(__uint_as_float(f2tf(o[dt][0] * i0)),
                                         __uint_as_float(f2tf(o[dt][1] * i0)));
    *(float2*)&g_ctx[base + 8 * 1024] = make_float2(__uint_as_float(f2tf(o[dt][2] * i1)),
                                                    __uint_as_float(f2tf(o[dt][3] * i1)));
  }
}

// ------------------------------------------------------------
// LayerNorm over D=1024
// ------------------------------------------------------------
__global__ __launch_bounds__(256) void ln_kernel(const float* __restrict__ gamma,
                                                 const float* __restrict__ beta,
                                                 float* __restrict__ out) {
  __shared__ float red[8];
  __shared__ float bc;
  const int row = blockIdx.x, tid = threadIdx.x;
  const float* x = g_pre + (size_t)row * D_;
  float4 v = *(const float4*)&x[tid * 4];

  float s = v.x + v.y + v.z + v.w;
#pragma unroll
  for (int off = 16; off > 0; off >>= 1) s += __shfl_xor_sync(0xffffffffu, s, off);
  if ((tid & 31) == 0) red[tid >> 5] = s;
  __syncthreads();
  if (tid == 0) {
    float t = 0.f;
#pragma unroll
    for (int i = 0; i < 8; i++) t += red[i];
    bc = t * (1.0f / D_);
  }
  __syncthreads();
  float mu = bc;

  float dx = v.x - mu, dy = v.y - mu, dz = v.z - mu, dw = v.w - mu;
  float sq = dx * dx + dy * dy + dz * dz + dw * dw;
#pragma unroll
  for (int off = 16; off > 0; off >>= 1) sq += __shfl_xor_sync(0xffffffffu, sq, off);
  __syncthreads();
  if ((tid & 31) == 0) red[tid >> 5] = sq;
  __syncthreads();
  if (tid == 0) {
    float t = 0.f;
#pragma unroll
    for (int i = 0; i < 8; i++) t += red[i];
    bc = rsqrtf(t * (1.0f / D_) + 1e-5f);
  }
  __syncthreads();
  float inv = bc;

  float4 g = *(const float4*)&gamma[tid * 4];
  float4 be = *(const float4*)&beta[tid * 4];
  *(float4*)&out[(size_t)row * D_ + tid * 4] =
      make_float4(dx * inv * g.x + be.x, dy * inv * g.y + be.y,
                  dz * inv * g.z + be.z, dw * inv * g.w + be.w);
}

// ------------------------------------------------------------
extern "C" void kernel_launch(void* const* d_in, const int* in_sizes, int n_in,
                              void* d_out, int out_size) {
  const float* xq    = (const float*)d_in[0];
  const float* xk    = (const float*)d_in[1];
  const float* xv    = (const float*)d_in[2];
  const int*   mask  = (const int*)  d_in[3];
  const float* wq    = (const float*)d_in[4];
  const float* wk    = (const float*)d_in[5];
  const float* wv    = (const float*)d_in[6];
  const float* wo    = (const float*)d_in[7];
  const float* gamma = (const float*)d_in[8];
  const float* beta  = (const float*)d_in[9];
  float* out = (float*)d_out;

  cudaFuncSetAttribute(gemm_tc_kernel, cudaFuncAttributeMaxDynamicSharedMemorySize, 65536);
  cudaFuncSetAttribute(attn_kernel, cudaFuncAttributeMaxDynamicSharedMemorySize, ATT_SMEM);

  cvt_x_kernel<<<dim3(4096, 3), 256>>>(xq, xk, xv);
  transpose_w_kernel<<<dim3(32, 32, 4), dim3(32, 8)>>>(wq, wk, wv, wo);
  gemm_tc_kernel<<<dim3(8, 32, 3), 256, 65536>>>(nullptr, 0);
  attn_kernel<<<dim3(32, 16, 2), 128, ATT_SMEM>>>(mask);
  gemm_tc_kernel<<<dim3(8, 32, 1), 256, 65536>>>(xq, 1);
  ln_kernel<<<M_, 256>>>(gamma, beta, out);
}

// round 6
// speedup vs baseline: 3.1720x; 1.2431x over previous
#include <cuda_runtime.h>
#include <cstdint>

#define B_ 2
#define S_ 2048
#define D_ 1024
#define H_ 16
#define DK_ 64
#define M_ (B_*S_)

// ---- static device scratch ----
__device__ float g_q[4194304], g_k[4194304], g_v[4194304];   // tf32 bits, [B,H,S,DK]
__device__ float g_ctx[4194304];                              // tf32 bits, [B*S, D]
__device__ float g_pre[4194304];                              // fp32
__device__ float g_wt[4194304];                               // tf32 bits, W^T x4
__device__ float g_xt[12582912];                              // tf32 bits, xq/xk/xv

// ---- helpers ----
__device__ __forceinline__ uint32_t f2tf(float f) {
  uint32_t u; asm("cvt.rna.tf32.f32 %0, %1;" : "=r"(u) : "f"(f)); return u;
}
__device__ __forceinline__ uint32_t smem_u32(const void* p) {
  uint32_t a;
  asm("{ .reg .u64 t; cvta.to.shared.u64 t, %1; cvt.u32.u64 %0, t; }" : "=r"(a) : "l"(p));
  return a;
}
__device__ __forceinline__ void cp16(uint32_t d, const void* s) {
  asm volatile("cp.async.cg.shared.global [%0], [%1], 16;" :: "r"(d), "l"(s) : "memory");
}
__device__ __forceinline__ void mma8(float* d, const uint32_t* a, const uint32_t* b) {
  asm volatile(
    "mma.sync.aligned.m16n8k8.row.col.f32.tf32.tf32.f32 "
    "{%0,%1,%2,%3}, {%4,%5,%6,%7}, {%8,%9}, {%0,%1,%2,%3};"
    : "+f"(d[0]), "+f"(d[1]), "+f"(d[2]), "+f"(d[3])
    : "r"(a[0]), "r"(a[1]), "r"(a[2]), "r"(a[3]), "r"(b[0]), "r"(b[1]));
}
__device__ __forceinline__ int swz32(int r, int k) {
  return r * 32 + (((((k) >> 2) ^ (r & 7)) << 2) | (k & 3));
}

// ============================================================
// Prepass: convert inputs to tf32 bits
// ============================================================
__global__ __launch_bounds__(256) void cvt_x_kernel(
    const float* __restrict__ xq, const float* __restrict__ xk,
    const float* __restrict__ xv) {
  const float* x = (blockIdx.y == 0) ? xq : (blockIdx.y == 1) ? xk : xv;
  float* o = g_xt + (size_t)blockIdx.y * 4194304;
  size_t i = ((size_t)blockIdx.x * 256 + threadIdx.x) * 4;
  float4 v = *(const float4*)&x[i];
  *(uint4*)&o[i] = make_uint4(f2tf(v.x), f2tf(v.y), f2tf(v.z), f2tf(v.w));
}

// ============================================================
// Weight transpose + tf32 convert: g_wt[z][n][k] = tf32(W_z[k][n])
// ============================================================
__global__ __launch_bounds__(256) void transpose_w_kernel(
    const float* __restrict__ wq, const float* __restrict__ wk,
    const float* __restrict__ wv, const float* __restrict__ wo) {
  __shared__ float t[32][33];
  const int z = blockIdx.z;
  const float* W = (z == 0) ? wq : (z == 1) ? wk : (z == 2) ? wv : wo;
  float* O = g_wt + ((size_t)z << 20);
  const int n0 = blockIdx.x * 32, k0 = blockIdx.y * 32;
  const int tx = threadIdx.x, ty = threadIdx.y;
#pragma unroll
  for (int r = 0; r < 32; r += 8)
    t[ty + r][tx] = W[(size_t)(k0 + ty + r) * 1024 + n0 + tx];
  __syncthreads();
#pragma unroll
  for (int r = 0; r < 32; r += 8)
    O[(size_t)(n0 + ty + r) * 1024 + k0 + tx] = __uint_as_float(f2tf(t[tx][ty + r]));
}

// ============================================================
// tf32 mma.sync GEMM (unchanged, known-good)
// ============================================================
__global__ __launch_bounds__(256) void gemm_tc_kernel(const float* __restrict__ resid,
                                                      int mode) {
  extern __shared__ uint32_t dsm[];
  const int tid = threadIdx.x, lane = tid & 31, wid = tid >> 5;
  const int wm = wid & 3, wn = wid >> 2;
  const int z = blockIdx.z;
  const float* A = (mode == 0) ? (g_xt + (size_t)z * 4194304) : g_ctx;
  const float* Wt = g_wt + ((size_t)(mode == 0 ? z : 3) << 20);
  const int m0 = blockIdx.y * 128, n0 = blockIdx.x * 128;
  const uint32_t sbase = smem_u32(dsm);

  float acc[2][8][4];
#pragma unroll
  for (int i = 0; i < 2; i++)
#pragma unroll
    for (int j = 0; j < 8; j++)
#pragma unroll
      for (int q = 0; q < 4; q++) acc[i][j][q] = 0.f;

#define GEMM_ISSUE(st, kc) do {                                                \
    uint32_t _b = sbase + (st) * 32768;                                        \
    _Pragma("unroll")                                                          \
    for (int t = 0; t < 4; ++t) {                                              \
      int idx = tid + t * 256;                                                 \
      int row = idx >> 3, g = idx & 7;                                         \
      uint32_t off = (uint32_t)(row * 32 + ((g ^ (row & 7)) << 2)) * 4;        \
      cp16(_b + off, A + (size_t)(m0 + row) * 1024 + (kc) + g * 4);            \
      cp16(_b + 16384 + off, Wt + (size_t)(n0 + row) * 1024 + (kc) + g * 4);   \
    }                                                                          \
    asm volatile("cp.async.commit_group;" ::: "memory");                       \
  } while (0)

  GEMM_ISSUE(0, 0);

  for (int kt = 0; kt < 32; ++kt) {
    const int s = kt & 1;
    if (kt < 31) {
      GEMM_ISSUE(s ^ 1, (kt + 1) * 32);
      asm volatile("cp.async.wait_group 1;" ::: "memory");
    } else {
      asm volatile("cp.async.wait_group 0;" ::: "memory");
    }
    __syncthreads();
    const uint32_t* As = dsm + s * 8192;
    const uint32_t* Bs = As + 4096;
#pragma unroll
    for (int ks = 0; ks < 4; ++ks) {
      const int k0 = ks * 8 + (lane & 3);
      uint32_t af[2][4];
#pragma unroll
      for (int tm = 0; tm < 2; ++tm) {
        int m = wm * 32 + tm * 16 + (lane >> 2);
        af[tm][0] = As[swz32(m, k0)];
        af[tm][1] = As[swz32(m + 8, k0)];
        af[tm][2] = As[swz32(m, k0 + 4)];
        af[tm][3] = As[swz32(m + 8, k0 + 4)];
      }
#pragma unroll
      for (int tn = 0; tn < 8; ++tn) {
        int n = wn * 64 + tn * 8 + (lane >> 2);
        uint32_t bf[2] = {Bs[swz32(n, k0)], Bs[swz32(n, k0 + 4)]};
        mma8(acc[0][tn], af[0], bf);
        mma8(acc[1][tn], af[1], bf);
      }
    }
    __syncthreads();
  }

#pragma unroll
  for (int tm = 0; tm < 2; ++tm) {
#pragma unroll
    for (int tn = 0; tn < 8; ++tn) {
      const int m = m0 + wm * 32 + tm * 16 + (lane >> 2);
      const int n = n0 + wn * 64 + tn * 8 + 2 * (lane & 3);
      float* c = acc[tm][tn];
      if (mode == 0) {
        float* O = (z == 0) ? g_q : (z == 1) ? g_k : g_v;
        const int b = m >> 11, sq = m & 2047, h = n >> 6, dk = n & 63;
        *(float2*)&O[(((size_t)b * H_ + h) * S_ + sq) * 64 + dk] =
            make_float2(__uint_as_float(f2tf(c[0])), __uint_as_float(f2tf(c[1])));
        *(float2*)&O[(((size_t)b * H_ + h) * S_ + sq + 8) * 64 + dk] =
            make_float2(__uint_as_float(f2tf(c[2])), __uint_as_float(f2tf(c[3])));
      } else {
        float2 r0 = *(const float2*)&resid[(size_t)m * 1024 + n];
        float2 r1 = *(const float2*)&resid[(size_t)(m + 8) * 1024 + n];
        *(float2*)&g_pre[(size_t)m * 1024 + n] = make_float2(c[0] + r0.x, c[1] + r0.y);
        *(float2*)&g_pre[(size_t)(m + 8) * 1024 + n] = make_float2(c[2] + r1.x, c[3] + r1.y);
      }
    }
  }
}

// ============================================================
// Flash attention v3: 128 threads, 4 warps, warp = 16q x 64keys.
// Padded affine smem layouts -> immediate-offset, conflict-free LDS:
//   K tile: row (key) stride 68 words (272B)   bank = qr*4+qq
//   V tile: row (dk)  stride 72 words (288B)   bank = qq*8+(qr>>2)*4+(qr&3)
// Double-buffered cp.async (prefetch kt+1 during kt compute).
// smem: 2 stages x (17408 + 18432) = 71680 B. Q staged in stage1 V area.
// ============================================================
#define KSTR 68     // words
#define VSTR 72     // words
#define STGW 8960   // stage stride in words (35840 B)
#define VOFW 4352   // V offset within stage, words (17408 B)
#define QOFW 13312  // Q staging offset, words (stage1 V area, 53248 B)
#define ATT_SMEM 71680
__global__ __launch_bounds__(128, 3) void attn_kernel(const int* __restrict__ mask) {
  extern __shared__ uint32_t sm[];
  const uint32_t sb = smem_u32(sm);

  const int tid = threadIdx.x, lane = tid & 31, w = tid >> 5;
  const int qt = blockIdx.x, h = blockIdx.y, b = blockIdx.z;
  const float* Qg = g_q + ((size_t)(b * H_ + h) * S_ + qt * 64) * 64;
  const float* Kg = g_k + (size_t)(b * H_ + h) * S_ * 64;
  const float* Vg = g_v + (size_t)(b * H_ + h) * S_ * 64;
  const int* mkb = mask + (size_t)b * S_ * S_;

  const int qr = lane >> 2;   // 0..7
  const int qq = lane & 3;    // 0..3

#define KV_ISSUE(kt, st) do {                                                  \
    uint32_t kb = sb + (st) * (STGW * 4);                                      \
    uint32_t vb = kb + (VOFW * 4);                                             \
    _Pragma("unroll")                                                          \
    for (int t = 0; t < 8; ++t) {                                              \
      int idx = tid + t * 128;                                                 \
      int row = idx >> 4, c = idx & 15;                                        \
      size_t gof = (size_t)((kt) * 64 + row) * 64 + c * 4;                     \
      cp16(kb + row * 272 + c * 16, Kg + gof);                                 \
      cp16(vb + row * 288 + c * 16, Vg + gof);                                 \
    }                                                                          \
    asm volatile("cp.async.commit_group;" ::: "memory");                       \
  } while (0)

  // prefetch kt=0 and stage Q (into stage1 V area) concurrently
  KV_ISSUE(0, 0);
#pragma unroll
  for (int t = 0; t < 8; ++t) {
    int idx = tid + t * 128;
    int row = idx >> 4, g = idx & 15;
    uint4 v = *(const uint4*)&Qg[row * 64 + g * 4];
    *(uint4*)&sm[QOFW + row * KSTR + g * 4] = v;
  }
  __syncthreads();

  // read Q A-fragments (K-layout: word = r*68 + ks*8 + b4 + qq)
  const uint32_t* Qp = sm + QOFW + (w * 16 + qr) * KSTR + qq;
  uint32_t qa[8][4];
#pragma unroll
  for (int ks = 0; ks < 8; ++ks) {
    qa[ks][0] = Qp[ks * 8];
    qa[ks][1] = Qp[8 * KSTR + ks * 8];
    qa[ks][2] = Qp[ks * 8 + 4];
    qa[ks][3] = Qp[8 * KSTR + ks * 8 + 4];
  }
  __syncthreads();  // qa reads done before kt=1 prefetch overwrites stage1

  float o[8][4];
#pragma unroll
  for (int i = 0; i < 8; i++)
#pragma unroll
    for (int j = 0; j < 4; j++) o[i][j] = 0.f;
  float m0r = -1e30f, m1r = -1e30f, l0r = 0.f, l1r = 0.f;
  const int r0 = w * 16 + qr;
  const int qg0 = qt * 64 + r0;
  const int srcA = (lane & ~3) | (qq >> 1);
  const int srcB = srcA + 2;

  for (int kt = 0; kt < 32; ++kt) {
    const int s = kt & 1;
    if (kt < 31) {
      KV_ISSUE(kt + 1, s ^ 1);
      asm volatile("cp.async.wait_group 1;" ::: "memory");
    } else {
      asm volatile("cp.async.wait_group 0;" ::: "memory");
    }
    __syncthreads();

    // per-stage fragment base pointers (affine -> immediate offsets)
    const uint32_t* Kp = sm + s * STGW + qr * KSTR + qq;
    const uint32_t* Vp = sm + s * STGW + VOFW + qq * VSTR + (qr >> 2) * 4 + (qr & 3);

    // S = Q K^T : warp tile 16q x 64keys
    float sc[8][4];
#pragma unroll
    for (int i = 0; i < 8; i++)
#pragma unroll
      for (int j = 0; j < 4; j++) sc[i][j] = 0.f;
#pragma unroll
    for (int ks = 0; ks < 8; ++ks) {
#pragma unroll
      for (int tn = 0; tn < 8; ++tn) {
        uint32_t bf[2] = {Kp[tn * 8 * KSTR + ks * 8], Kp[tn * 8 * KSTR + ks * 8 + 4]};
        mma8(sc[tn], qa[ks], bf);
      }
    }

    // scale + mask
#pragma unroll
    for (int tn = 0; tn < 8; ++tn) {
      int col = kt * 64 + tn * 8 + 2 * qq;
      int2 mk0 = *(const int2*)&mkb[(size_t)qg0 * S_ + col];
      int2 mk1 = *(const int2*)&mkb[(size_t)(qg0 + 8) * S_ + col];
      sc[tn][0] = mk0.x ? -1e9f : sc[tn][0] * 0.125f;
      sc[tn][1] = mk0.y ? -1e9f : sc[tn][1] * 0.125f;
      sc[tn][2] = mk1.x ? -1e9f : sc[tn][2] * 0.125f;
      sc[tn][3] = mk1.y ? -1e9f : sc[tn][3] * 0.125f;
    }

    // warp-local online softmax
    float mx0 = -1e30f, mx1 = -1e30f;
#pragma unroll
    for (int tn = 0; tn < 8; ++tn) {
      mx0 = fmaxf(mx0, fmaxf(sc[tn][0], sc[tn][1]));
      mx1 = fmaxf(mx1, fmaxf(sc[tn][2], sc[tn][3]));
    }
    mx0 = fmaxf(mx0, __shfl_xor_sync(0xffffffffu, mx0, 1));
    mx0 = fmaxf(mx0, __shfl_xor_sync(0xffffffffu, mx0, 2));
    mx1 = fmaxf(mx1, __shfl_xor_sync(0xffffffffu, mx1, 1));
    mx1 = fmaxf(mx1, __shfl_xor_sync(0xffffffffu, mx1, 2));
    float mn0 = fmaxf(m0r, mx0), mn1 = fmaxf(m1r, mx1);
    float f0 = __expf(m0r - mn0), f1 = __expf(m1r - mn1);
    m0r = mn0; m1r = mn1;

    float ls0 = 0.f, ls1 = 0.f;
#pragma unroll
    for (int tn = 0; tn < 8; ++tn) {
      sc[tn][0] = __expf(sc[tn][0] - mn0); ls0 += sc[tn][0];
      sc[tn][1] = __expf(sc[tn][1] - mn0); ls0 += sc[tn][1];
      sc[tn][2] = __expf(sc[tn][2] - mn1); ls1 += sc[tn][2];
      sc[tn][3] = __expf(sc[tn][3] - mn1); ls1 += sc[tn][3];
    }
    ls0 += __shfl_xor_sync(0xffffffffu, ls0, 1);
    ls0 += __shfl_xor_sync(0xffffffffu, ls0, 2);
    ls1 += __shfl_xor_sync(0xffffffffu, ls1, 1);
    ls1 += __shfl_xor_sync(0xffffffffu, ls1, 2);
    l0r = l0r * f0 + ls0;
    l1r = l1r * f1 + ls1;
#pragma unroll
    for (int dt = 0; dt < 8; ++dt) {
      o[dt][0] *= f0; o[dt][1] *= f0; o[dt][2] *= f1; o[dt][3] *= f1;
    }

    // P C-frag -> A-frag in registers (intra-quad shuffles), then PV
#pragma unroll
    for (int ks = 0; ks < 8; ++ks) {
      float t00 = __shfl_sync(0xffffffffu, sc[ks][0], srcA);
      float t01 = __shfl_sync(0xffffffffu, sc[ks][1], srcA);
      float t02 = __shfl_sync(0xffffffffu, sc[ks][0], srcB);
      float t03 = __shfl_sync(0xffffffffu, sc[ks][1], srcB);
      float t10 = __shfl_sync(0xffffffffu, sc[ks][2], srcA);
      float t11 = __shfl_sync(0xffffffffu, sc[ks][3], srcA);
      float t12 = __shfl_sync(0xffffffffu, sc[ks][2], srcB);
      float t13 = __shfl_sync(0xffffffffu, sc[ks][3], srcB);
      uint32_t pa[4];
      pa[0] = f2tf((qq & 1) ? t01 : t00);
      pa[1] = f2tf((qq & 1) ? t11 : t10);
      pa[2] = f2tf((qq & 1) ? t03 : t02);
      pa[3] = f2tf((qq & 1) ? t13 : t12);
#pragma unroll
      for (int dt = 0; dt < 8; ++dt) {
        uint32_t vf[2] = {Vp[ks * 8 * VSTR + dt * 8], Vp[ks * 8 * VSTR + 4 * VSTR + dt * 8]};
        mma8(o[dt], pa, vf);
      }
    }
    __syncthreads();  // stage-s reads done before kt+1 prefetch overwrites it
  }

  // epilogue -> g_ctx (tf32 bits, merged heads)
  const float i0 = 1.f / l0r, i1 = 1.f / l1r;
#pragma unroll
  for (int dt = 0; dt < 8; ++dt) {
    int dk = dt * 8 + 2 * qq;
    size_t base = ((size_t)b * S_ + qt * 64 + r0) * 1024 + h * 64 + dk;
    *(float2*)&g_ctx[base] = make_float2(__uint_as_float(f2tf(o[dt][0] * i0)),
                                         __uint_as_float(f2tf(o[dt][1] * i0)));
    *(float2*)&g_ctx[base + 8 * 1024] = make_float2(__uint_as_float(f2tf(o[dt][2] * i1)),
                                                    __uint_as_float(f2tf(o[dt][3] * i1)));
  }
}

// ------------------------------------------------------------
// LayerNorm over D=1024
// ------------------------------------------------------------
__global__ __launch_bounds__(256) void ln_kernel(const float* __restrict__ gamma,
                                                 const float* __restrict__ beta,
                                                 float* __restrict__ out) {
  __shared__ float red[8];
  __shared__ float bc;
  const int row = blockIdx.x, tid = threadIdx.x;
  const float* x = g_pre + (size_t)row * D_;
  float4 v = *(const float4*)&x[tid * 4];

  float s = v.x + v.y + v.z + v.w;
#pragma unroll
  for (int off = 16; off > 0; off >>= 1) s += __shfl_xor_sync(0xffffffffu, s, off);
  if ((tid & 31) == 0) red[tid >> 5] = s;
  __syncthreads();
  if (tid == 0) {
    float t = 0.f;
#pragma unroll
    for (int i = 0; i < 8; i++) t += red[i];
    bc = t * (1.0f / D_);
  }
  __syncthreads();
  float mu = bc;

  float dx = v.x - mu, dy = v.y - mu, dz = v.z - mu, dw = v.w - mu;
  float sq = dx * dx + dy * dy + dz * dz + dw * dw;
#pragma unroll
  for (int off = 16; off > 0; off >>= 1) sq += __shfl_xor_sync(0xffffffffu, sq, off);
  __syncthreads();
  if ((tid & 31) == 0) red[tid >> 5] = sq;
  __syncthreads();
  if (tid == 0) {
    float t = 0.f;
#pragma unroll
    for (int i = 0; i < 8; i++) t += red[i];
    bc = rsqrtf(t * (1.0f / D_) + 1e-5f);
  }
  __syncthreads();
  float inv = bc;

  float4 g = *(const float4*)&gamma[tid * 4];
  float4 be = *(const float4*)&beta[tid * 4];
  *(float4*)&out[(size_t)row * D_ + tid * 4] =
      make_float4(dx * inv * g.x + be.x, dy * inv * g.y + be.y,
                  dz * inv * g.z + be.z, dw * inv * g.w + be.w);
}

// ------------------------------------------------------------
extern "C" void kernel_launch(void* const* d_in, const int* in_sizes, int n_in,
                              void* d_out, int out_size) {
  const float* xq    = (const float*)d_in[0];
  const float* xk    = (const float*)d_in[1];
  const float* xv    = (const float*)d_in[2];
  const int*   mask  = (const int*)  d_in[3];
  const float* wq    = (const float*)d_in[4];
  const float* wk    = (const float*)d_in[5];
  const float* wv    = (const float*)d_in[6];
  const float* wo    = (const float*)d_in[7];
  const float* gamma = (const float*)d_in[8];
  const float* beta  = (const float*)d_in[9];
  float* out = (float*)d_out;

  cudaFuncSetAttribute(gemm_tc_kernel, cudaFuncAttributeMaxDynamicSharedMemorySize, 65536);
  cudaFuncSetAttribute(attn_kernel, cudaFuncAttributeMaxDynamicSharedMemorySize, ATT_SMEM);

  cvt_x_kernel<<<dim3(4096, 3), 256>>>(xq, xk, xv);
  transpose_w_kernel<<<dim3(32, 32, 4), dim3(32, 8)>>>(wq, wk, wv, wo);
  gemm_tc_kernel<<<dim3(8, 32, 3), 256, 65536>>>(nullptr, 0);
  attn_kernel<<<dim3(32, 16, 2), 128, ATT_SMEM>>>(mask);
  gemm_tc_kernel<<<dim3(8, 32, 1), 256, 65536>>>(xq, 1);
  ln_kernel<<<M_, 256>>>(gamma, beta, out);
}

// round 7
// speedup vs baseline: 5.2485x; 1.6547x over previous
#include <cuda_runtime.h>
#include <cuda_bf16.h>
#include <cstdint>

#define B_ 2
#define S_ 2048
#define D_ 1024
#define H_ 16
#define DK_ 64
#define M_ (B_*S_)

// ---- static device scratch ----
__device__ __nv_bfloat16 g_q[4194304];    // [B,H,S,DK]
__device__ __nv_bfloat16 g_k[4194304];    // [B,H,S,DK]
__device__ __nv_bfloat16 g_v[4194304];    // [B,H,DK,S]  (transposed!)
__device__ __nv_bfloat16 g_ctx[4194304];  // [B*S, D]
__device__ __nv_bfloat16 g_wt[4194304];   // W^T x4 [n][k]
__device__ __nv_bfloat16 g_xt[12582912];  // xq/xk/xv bf16
__device__ float g_pre[4194304];          // fp32 pre-LN

// ---- helpers ----
__device__ __forceinline__ uint32_t pk2(float hi, float lo) {
  uint32_t r; asm("cvt.rn.bf16x2.f32 %0, %1, %2;" : "=r"(r) : "f"(hi), "f"(lo));
  return r;
}
__device__ __forceinline__ uint32_t smem_u32(const void* p) {
  uint32_t a;
  asm("{ .reg .u64 t; cvta.to.shared.u64 t, %1; cvt.u32.u64 %0, t; }" : "=r"(a) : "l"(p));
  return a;
}
__device__ __forceinline__ void cp16(uint32_t d, const void* s) {
  asm volatile("cp.async.cg.shared.global [%0], [%1], 16;" :: "r"(d), "l"(s) : "memory");
}
__device__ __forceinline__ void mma16(float* d, const uint32_t* a, const uint32_t* b) {
  asm volatile(
    "mma.sync.aligned.m16n8k16.row.col.f32.bf16.bf16.f32 "
    "{%0,%1,%2,%3}, {%4,%5,%6,%7}, {%8,%9}, {%0,%1,%2,%3};"
    : "+f"(d[0]), "+f"(d[1]), "+f"(d[2]), "+f"(d[3])
    : "r"(a[0]), "r"(a[1]), "r"(a[2]), "r"(a[3]), "r"(b[0]), "r"(b[1]));
}

// ============================================================
// Prepass: fp32 -> bf16
// ============================================================
__global__ __launch_bounds__(256) void cvt_x_kernel(
    const float* __restrict__ xq, const float* __restrict__ xk,
    const float* __restrict__ xv) {
  const float* x = (blockIdx.y == 0) ? xq : (blockIdx.y == 1) ? xk : xv;
  uint32_t* o32 = (uint32_t*)(g_xt + (size_t)blockIdx.y * 4194304);
  size_t i = ((size_t)blockIdx.x * 256 + threadIdx.x) * 4;
  float4 v = *(const float4*)&x[i];
  o32[(i >> 1)]     = pk2(v.y, v.x);
  o32[(i >> 1) + 1] = pk2(v.w, v.z);
}

// ============================================================
// Weight transpose + bf16: g_wt[z][n][k] = bf16(W_z[k][n])
// ============================================================
__global__ __launch_bounds__(256) void transpose_w_kernel(
    const float* __restrict__ wq, const float* __restrict__ wk,
    const float* __restrict__ wv, const float* __restrict__ wo) {
  __shared__ float t[32][33];
  const int z = blockIdx.z;
  const float* W = (z == 0) ? wq : (z == 1) ? wk : (z == 2) ? wv : wo;
  __nv_bfloat16* O = g_wt + ((size_t)z << 20);
  const int n0 = blockIdx.x * 32, k0 = blockIdx.y * 32;
  const int tx = threadIdx.x, ty = threadIdx.y;
#pragma unroll
  for (int r = 0; r < 32; r += 8)
    t[ty + r][tx] = W[(size_t)(k0 + ty + r) * 1024 + n0 + tx];
  __syncthreads();
#pragma unroll
  for (int r = 0; r < 32; r += 8)
    O[(size_t)(n0 + ty + r) * 1024 + k0 + tx] = __float2bfloat16_rn(t[tx][ty + r]);
}

// ============================================================
// bf16 mma.sync GEMM: C[128,128]/CTA, 8 warps x (32m x 64n), BK=64.
// Padded affine smem (row stride 36 words), cp.async double-buffered.
// mode 0: QKV -> g_q/g_k bf16 [B,H,S,DK]; g_v bf16 TRANSPOSED [B,H,DK,S]
// mode 1: out-proj (A=g_ctx) + resid -> g_pre fp32
// smem: 2 stages x (A 4608w + B 4608w) = 73728 B
// ============================================================
#define GEMM_SMEM 73728
__global__ __launch_bounds__(256) void gemm_tc_kernel(const float* __restrict__ resid,
                                                      int mode) {
  extern __shared__ uint32_t dsm[];
  const int tid = threadIdx.x, lane = tid & 31, wid = tid >> 5;
  const int qr = lane >> 2, qq = lane & 3;
  const int wm = wid & 3, wn = wid >> 2;
  const int z = blockIdx.z;
  const __nv_bfloat16* A = (mode == 0) ? (g_xt + (size_t)z * 4194304) : g_ctx;
  const __nv_bfloat16* Wt = g_wt + ((size_t)(mode == 0 ? z : 3) << 20);
  const int m0 = blockIdx.y * 128, n0 = blockIdx.x * 128;
  const uint32_t sbase = smem_u32(dsm);

  float acc[2][8][4];
#pragma unroll
  for (int i = 0; i < 2; i++)
#pragma unroll
    for (int j = 0; j < 8; j++)
#pragma unroll
      for (int q = 0; q < 4; q++) acc[i][j][q] = 0.f;

#define GEMM_ISSUE(st, kc) do {                                                \
    uint32_t _b = sbase + (st) * 36864;                                        \
    _Pragma("unroll")                                                          \
    for (int t = 0; t < 4; ++t) {                                              \
      int idx = tid + t * 256;                                                 \
      int row = idx >> 3, c = idx & 7;                                         \
      cp16(_b + row * 144 + c * 16, A + (size_t)(m0 + row) * 1024 + (kc) + c * 8);   \
      cp16(_b + 18432 + row * 144 + c * 16,                                    \
           Wt + (size_t)(n0 + row) * 1024 + (kc) + c * 8);                     \
    }                                                                          \
    asm volatile("cp.async.commit_group;" ::: "memory");                       \
  } while (0)

  GEMM_ISSUE(0, 0);

  for (int kt = 0; kt < 16; ++kt) {
    const int s = kt & 1;
    if (kt < 15) {
      GEMM_ISSUE(s ^ 1, (kt + 1) * 64);
      asm volatile("cp.async.wait_group 1;" ::: "memory");
    } else {
      asm volatile("cp.async.wait_group 0;" ::: "memory");
    }
    __syncthreads();
    const uint32_t* As = dsm + s * 9216;
    const uint32_t* Bs = As + 4608;
#pragma unroll
    for (int ks = 0; ks < 4; ++ks) {
      const int kw = ks * 8 + qq;
      uint32_t af[2][4];
#pragma unroll
      for (int tm = 0; tm < 2; ++tm) {
        const uint32_t* p = As + (wm * 32 + tm * 16 + qr) * 36 + kw;
        af[tm][0] = p[0]; af[tm][1] = p[288]; af[tm][2] = p[4]; af[tm][3] = p[292];
      }
#pragma unroll
      for (int tn = 0; tn < 8; ++tn) {
        const uint32_t* p = Bs + (wn * 64 + tn * 8 + qr) * 36 + kw;
        uint32_t bf[2] = {p[0], p[4]};
        mma16(acc[0][tn], af[0], bf);
        mma16(acc[1][tn], af[1], bf);
      }
    }
    __syncthreads();
  }

#pragma unroll
  for (int tm = 0; tm < 2; ++tm) {
#pragma unroll
    for (int tn = 0; tn < 8; ++tn) {
      const int m = m0 + wm * 32 + tm * 16 + qr;
      const int n = n0 + wn * 64 + tn * 8 + 2 * qq;
      float* c = acc[tm][tn];
      if (mode == 0) {
        const int b = m >> 11, sq = m & 2047, h = n >> 6, dk = n & 63;
        if (z < 2) {
          uint32_t* O32 = (uint32_t*)(z == 0 ? g_q : g_k);
          size_t wi = (((size_t)(b * 16 + h) * 2048 + sq) << 5) + (dk >> 1);
          O32[wi] = pk2(c[1], c[0]);
          O32[wi + 256] = pk2(c[3], c[2]);   // sq+8 -> +8*32 words
        } else {
          __nv_bfloat16* V = g_v + ((size_t)(b * 16 + h) * 64 + dk) * 2048 + sq;
          V[0]    = __float2bfloat16_rn(c[0]);
          V[2048] = __float2bfloat16_rn(c[1]);   // dk+1
          V[8]    = __float2bfloat16_rn(c[2]);   // sq+8
          V[2056] = __float2bfloat16_rn(c[3]);
        }
      } else {
        float2 r0 = *(const float2*)&resid[(size_t)m * 1024 + n];
        float2 r1 = *(const float2*)&resid[(size_t)(m + 8) * 1024 + n];
        *(float2*)&g_pre[(size_t)m * 1024 + n] = make_float2(c[0] + r0.x, c[1] + r0.y);
        *(float2*)&g_pre[(size_t)(m + 8) * 1024 + n] = make_float2(c[2] + r1.x, c[3] + r1.y);
      }
    }
  }
}

// ============================================================
// Flash attention v4 (bf16 m16n8k16): 128 threads, 4 warps,
// warp = 16q x 64keys. PV A-frag = packed QK C-frag (NO shuffles).
// V staged from transposed g_v: smem tile [dk][key].
// Layout: row stride 36 words (72 bf16-pairs... 64 bf16 + pad).
// smem: Q 2304w + 2 stages x (K 2304w + V 2304w) = 46080 B
// ============================================================
#define ATT_SMEM 46080
__global__ __launch_bounds__(128, 4) void attn_kernel(const int* __restrict__ mask) {
  extern __shared__ uint32_t sm[];
  const uint32_t sb = smem_u32(sm);

  const int tid = threadIdx.x, lane = tid & 31, w = tid >> 5;
  const int qr = lane >> 2, qq = lane & 3;
  const int qt = blockIdx.x, h = blockIdx.y, b = blockIdx.z;
  const __nv_bfloat16* Qg = g_q + ((size_t)(b * 16 + h) * 2048 + qt * 64) * 64;
  const __nv_bfloat16* Kg = g_k + (size_t)(b * 16 + h) * 2048 * 64;
  const __nv_bfloat16* Vg = g_v + (size_t)(b * 16 + h) * 64 * 2048;
  const int* mkb = mask + (size_t)b * S_ * S_;

#define KV_ISSUE(kt, st) do {                                                  \
    uint32_t kb = sb + (2304 + (st) * 4608) * 4;                               \
    _Pragma("unroll")                                                          \
    for (int t = 0; t < 4; ++t) {                                              \
      int idx = tid + t * 128;                                                 \
      int row = idx >> 3, c = idx & 7;                                         \
      cp16(kb + row * 144 + c * 16, Kg + (size_t)((kt) * 64 + row) * 64 + c * 8);   \
      cp16(kb + 9216 + row * 144 + c * 16,                                     \
           Vg + (size_t)row * 2048 + (kt) * 64 + c * 8);                       \
    }                                                                          \
    asm volatile("cp.async.commit_group;" ::: "memory");                       \
  } while (0)

  // stage Q + prefetch kt=0 in one group
#pragma unroll
  for (int t = 0; t < 4; ++t) {
    int idx = tid + t * 128;
    int row = idx >> 3, c = idx & 7;
    cp16(sb + row * 144 + c * 16, Qg + row * 64 + c * 8);
  }
  KV_ISSUE(0, 0);
  asm volatile("cp.async.wait_group 0;" ::: "memory");
  __syncthreads();

  // Q A-fragments: qa[ks][.] , ks over 4 k16-groups of dk
  const uint32_t* Qp = sm + (w * 16 + qr) * 36 + qq;
  uint32_t qa[4][4];
#pragma unroll
  for (int ks = 0; ks < 4; ++ks) {
    qa[ks][0] = Qp[ks * 8];
    qa[ks][1] = Qp[288 + ks * 8];
    qa[ks][2] = Qp[ks * 8 + 4];
    qa[ks][3] = Qp[288 + ks * 8 + 4];
  }

  float o[8][4];
#pragma unroll
  for (int i = 0; i < 8; i++)
#pragma unroll
    for (int j = 0; j < 4; j++) o[i][j] = 0.f;
  float m0r = -1e30f, m1r = -1e30f, l0r = 0.f, l1r = 0.f;
  const int r0 = w * 16 + qr;
  const int qg0 = qt * 64 + r0;

  for (int kt = 0; kt < 32; ++kt) {
    const int s = kt & 1;
    if (kt < 31) {
      KV_ISSUE(kt + 1, s ^ 1);
      asm volatile("cp.async.wait_group 1;" ::: "memory");
    } else {
      asm volatile("cp.async.wait_group 0;" ::: "memory");
    }
    __syncthreads();

    const uint32_t* Kp = sm + 2304 + s * 4608 + qr * 36 + qq;
    const uint32_t* Vp = Kp + 2304;

    // S = Q K^T
    float sc[8][4];
#pragma unroll
    for (int i = 0; i < 8; i++)
#pragma unroll
      for (int j = 0; j < 4; j++) sc[i][j] = 0.f;
#pragma unroll
    for (int ks = 0; ks < 4; ++ks) {
#pragma unroll
      for (int tn = 0; tn < 8; ++tn) {
        uint32_t bf[2] = {Kp[tn * 288 + ks * 8], Kp[tn * 288 + ks * 8 + 4]};
        mma16(sc[tn], qa[ks], bf);
      }
    }

    // scale + mask
#pragma unroll
    for (int tn = 0; tn < 8; ++tn) {
      int col = kt * 64 + tn * 8 + 2 * qq;
      int2 mk0 = *(const int2*)&mkb[(size_t)qg0 * S_ + col];
      int2 mk1 = *(const int2*)&mkb[(size_t)(qg0 + 8) * S_ + col];
      sc[tn][0] = mk0.x ? -1e9f : sc[tn][0] * 0.125f;
      sc[tn][1] = mk0.y ? -1e9f : sc[tn][1] * 0.125f;
      sc[tn][2] = mk1.x ? -1e9f : sc[tn][2] * 0.125f;
      sc[tn][3] = mk1.y ? -1e9f : sc[tn][3] * 0.125f;
    }

    // warp-local online softmax
    float mx0 = -1e30f, mx1 = -1e30f;
#pragma unroll
    for (int tn = 0; tn < 8; ++tn) {
      mx0 = fmaxf(mx0, fmaxf(sc[tn][0], sc[tn][1]));
      mx1 = fmaxf(mx1, fmaxf(sc[tn][2], sc[tn][3]));
    }
    mx0 = fmaxf(mx0, __shfl_xor_sync(0xffffffffu, mx0, 1));
    mx0 = fmaxf(mx0, __shfl_xor_sync(0xffffffffu, mx0, 2));
    mx1 = fmaxf(mx1, __shfl_xor_sync(0xffffffffu, mx1, 1));
    mx1 = fmaxf(mx1, __shfl_xor_sync(0xffffffffu, mx1, 2));
    float mn0 = fmaxf(m0r, mx0), mn1 = fmaxf(m1r, mx1);
    float f0 = __expf(m0r - mn0), f1 = __expf(m1r - mn1);
    m0r = mn0; m1r = mn1;

    float ls0 = 0.f, ls1 = 0.f;
#pragma unroll
    for (int tn = 0; tn < 8; ++tn) {
      sc[tn][0] = __expf(sc[tn][0] - mn0); ls0 += sc[tn][0];
      sc[tn][1] = __expf(sc[tn][1] - mn0); ls0 += sc[tn][1];
      sc[tn][2] = __expf(sc[tn][2] - mn1); ls1 += sc[tn][2];
      sc[tn][3] = __expf(sc[tn][3] - mn1); ls1 += sc[tn][3];
    }
    ls0 += __shfl_xor_sync(0xffffffffu, ls0, 1);
    ls0 += __shfl_xor_sync(0xffffffffu, ls0, 2);
    ls1 += __shfl_xor_sync(0xffffffffu, ls1, 1);
    ls1 += __shfl_xor_sync(0xffffffffu, ls1, 2);
    l0r = l0r * f0 + ls0;
    l1r = l1r * f1 + ls1;
#pragma unroll
    for (int dt = 0; dt < 8; ++dt) {
      o[dt][0] *= f0; o[dt][1] *= f0; o[dt][2] *= f1; o[dt][3] *= f1;
    }

    // PV: A-frag = packed C-frag (no shuffles), B from transposed V tile
#pragma unroll
    for (int ks = 0; ks < 4; ++ks) {
      uint32_t pa[4];
      pa[0] = pk2(sc[2 * ks][1], sc[2 * ks][0]);
      pa[1] = pk2(sc[2 * ks][3], sc[2 * ks][2]);
      pa[2] = pk2(sc[2 * ks + 1][1], sc[2 * ks + 1][0]);
      pa[3] = pk2(sc[2 * ks + 1][3], sc[2 * ks + 1][2]);
#pragma unroll
      for (int dt = 0; dt < 8; ++dt) {
        uint32_t vf[2] = {Vp[dt * 288 + ks * 8], Vp[dt * 288 + ks * 8 + 4]};
        mma16(o[dt], pa, vf);
      }
    }
    __syncthreads();  // stage-s reads done before it is overwritten
  }

  // epilogue -> g_ctx bf16 (merged heads)
  const float i0 = 1.f / l0r, i1 = 1.f / l1r;
  uint32_t* C32 = (uint32_t*)g_ctx;
#pragma unroll
  for (int dt = 0; dt < 8; ++dt) {
    int dk = dt * 8 + 2 * qq;
    size_t wi = (((size_t)b * S_ + qt * 64 + r0) << 9) + ((h * 64 + dk) >> 1);
    C32[wi] = pk2(o[dt][1] * i0, o[dt][0] * i0);
    C32[wi + (8 << 9)] = pk2(o[dt][3] * i1, o[dt][2] * i1);
  }
}

// ------------------------------------------------------------
// LayerNorm over D=1024
// ------------------------------------------------------------
__global__ __launch_bounds__(256) void ln_kernel(const float* __restrict__ gamma,
                                                 const float* __restrict__ beta,
                                                 float* __restrict__ out) {
  __shared__ float red[8];
  __shared__ float bc;
  const int row = blockIdx.x, tid = threadIdx.x;
  const float* x = g_pre + (size_t)row * D_;
  float4 v = *(const float4*)&x[tid * 4];

  float s = v.x + v.y + v.z + v.w;
#pragma unroll
  for (int off = 16; off > 0; off >>= 1) s += __shfl_xor_sync(0xffffffffu, s, off);
  if ((tid & 31) == 0) red[tid >> 5] = s;
  __syncthreads();
  if (tid == 0) {
    float t = 0.f;
#pragma unroll
    for (int i = 0; i < 8; i++) t += red[i];
    bc = t * (1.0f / D_);
  }
  __syncthreads();
  float mu = bc;

  float dx = v.x - mu, dy = v.y - mu, dz = v.z - mu, dw = v.w - mu;
  float sq = dx * dx + dy * dy + dz * dz + dw * dw;
#pragma unroll
  for (int off = 16; off > 0; off >>= 1) sq += __shfl_xor_sync(0xffffffffu, sq, off);
  __syncthreads();
  if ((tid & 31) == 0) red[tid >> 5] = sq;
  __syncthreads();
  if (tid == 0) {
    float t = 0.f;
#pragma unroll
    for (int i = 0; i < 8; i++) t += red[i];
    bc = rsqrtf(t * (1.0f / D_) + 1e-5f);
  }
  __syncthreads();
  float inv = bc;

  float4 g = *(const float4*)&gamma[tid * 4];
  float4 be = *(const float4*)&beta[tid * 4];
  *(float4*)&out[(size_t)row * D_ + tid * 4] =
      make_float4(dx * inv * g.x + be.x, dy * inv * g.y + be.y,
                  dz * inv * g.z + be.z, dw * inv * g.w + be.w);
}

// ------------------------------------------------------------
extern "C" void kernel_launch(void* const* d_in, const int* in_sizes, int n_in,
                              void* d_out, int out_size) {
  const float* xq    = (const float*)d_in[0];
  const float* xk    = (const float*)d_in[1];
  const float* xv    = (const float*)d_in[2];
  const int*   mask  = (const int*)  d_in[3];
  const float* wq    = (const float*)d_in[4];
  const float* wk    = (const float*)d_in[5];
  const float* wv    = (const float*)d_in[6];
  const float* wo    = (const float*)d_in[7];
  const float* gamma = (const float*)d_in[8];
  const float* beta  = (const float*)d_in[9];
  float* out = (float*)d_out;

  cudaFuncSetAttribute(gemm_tc_kernel, cudaFuncAttributeMaxDynamicSharedMemorySize, GEMM_SMEM);
  cudaFuncSetAttribute(attn_kernel, cudaFuncAttributeMaxDynamicSharedMemorySize, ATT_SMEM);

  cvt_x_kernel<<<dim3(4096, 3), 256>>>(xq, xk, xv);
  transpose_w_kernel<<<dim3(32, 32, 4), dim3(32, 8)>>>(wq, wk, wv, wo);
  gemm_tc_kernel<<<dim3(8, 32, 3), 256, GEMM_SMEM>>>(nullptr, 0);
  attn_kernel<<<dim3(32, 16, 2), 128, ATT_SMEM>>>(mask);
  gemm_tc_kernel<<<dim3(8, 32, 1), 256, GEMM_SMEM>>>(xq, 1);
  ln_kernel<<<M_, 256>>>(gamma, beta, out);
}

// round 8
// speedup vs baseline: 5.6538x; 1.0772x over previous
#include <cuda_runtime.h>
#include <cuda_bf16.h>
#include <cstdint>

#define B_ 2
#define S_ 2048
#define D_ 1024
#define H_ 16
#define DK_ 64
#define M_ (B_*S_)

// Q pre-scale: 1/sqrt(DK) * log2(e)  (softmax runs in exp2 domain)
#define QSC 0.18033688011112042f
#define NEGB (-1.4426950408889634e9f)

// ---- static device scratch ----
__device__ __nv_bfloat16 g_q[4194304];    // [B,H,S,DK]  (pre-scaled by QSC)
__device__ __nv_bfloat16 g_k[4194304];    // [B,H,S,DK]
__device__ __nv_bfloat16 g_v[4194304];    // [B,H,DK,S]  (transposed!)
__device__ __nv_bfloat16 g_ctx[4194304];  // [B*S, D]
__device__ __nv_bfloat16 g_wt[4194304];   // W^T x4 [n][k]
__device__ __nv_bfloat16 g_xt[12582912];  // xq/xk/xv bf16
__device__ float g_pre[4194304];          // fp32 pre-LN
__device__ uint32_t g_mb[262144];         // bit-packed mask [B*S][64 words]

// ---- helpers ----
__device__ __forceinline__ uint32_t pk2(float hi, float lo) {
  uint32_t r; asm("cvt.rn.bf16x2.f32 %0, %1, %2;" : "=r"(r) : "f"(hi), "f"(lo));
  return r;
}
__device__ __forceinline__ float ex2(float x) {
  float r; asm("ex2.approx.f32 %0, %1;" : "=f"(r) : "f"(x)); return r;
}
__device__ __forceinline__ uint32_t smem_u32(const void* p) {
  uint32_t a;
  asm("{ .reg .u64 t; cvta.to.shared.u64 t, %1; cvt.u32.u64 %0, t; }" : "=r"(a) : "l"(p));
  return a;
}
__device__ __forceinline__ void cp16(uint32_t d, const void* s) {
  asm volatile("cp.async.cg.shared.global [%0], [%1], 16;" :: "r"(d), "l"(s) : "memory");
}
__device__ __forceinline__ void mma16(float* d, const uint32_t* a, const uint32_t* b) {
  asm volatile(
    "mma.sync.aligned.m16n8k16.row.col.f32.bf16.bf16.f32 "
    "{%0,%1,%2,%3}, {%4,%5,%6,%7}, {%8,%9}, {%0,%1,%2,%3};"
    : "+f"(d[0]), "+f"(d[1]), "+f"(d[2]), "+f"(d[3])
    : "r"(a[0]), "r"(a[1]), "r"(a[2]), "r"(a[3]), "r"(b[0]), "r"(b[1]));
}

// ============================================================
// Prepass: fp32 -> bf16
// ============================================================
__global__ __launch_bounds__(256) void cvt_x_kernel(
    const float* __restrict__ xq, const float* __restrict__ xk,
    const float* __restrict__ xv) {
  const float* x = (blockIdx.y == 0) ? xq : (blockIdx.y == 1) ? xk : xv;
  uint32_t* o32 = (uint32_t*)(g_xt + (size_t)blockIdx.y * 4194304);
  size_t i = ((size_t)blockIdx.x * 256 + threadIdx.x) * 4;
  float4 v = *(const float4*)&x[i];
  o32[(i >> 1)]     = pk2(v.y, v.x);
  o32[(i >> 1) + 1] = pk2(v.w, v.z);
}

// ============================================================
// Prepass: bit-pack mask. word w covers keys [w*32, w*32+32)
// ============================================================
__global__ __launch_bounds__(256) void pack_mask_kernel(const int* __restrict__ m) {
  size_t w = (size_t)blockIdx.x * 256 + threadIdx.x;
  const int4* p = (const int4*)(m + w * 32);
  uint32_t bits = 0;
#pragma unroll
  for (int i = 0; i < 8; ++i) {
    int4 v = p[i];
    bits |= (v.x ? 1u : 0u) << (4 * i)
          | (v.y ? 1u : 0u) << (4 * i + 1)
          | (v.z ? 1u : 0u) << (4 * i + 2)
          | (v.w ? 1u : 0u) << (4 * i + 3);
  }
  g_mb[w] = bits;
}

// ============================================================
// Weight transpose + bf16: g_wt[z][n][k] = bf16(W_z[k][n])
// ============================================================
__global__ __launch_bounds__(256) void transpose_w_kernel(
    const float* __restrict__ wq, const float* __restrict__ wk,
    const float* __restrict__ wv, const float* __restrict__ wo) {
  __shared__ float t[32][33];
  const int z = blockIdx.z;
  const float* W = (z == 0) ? wq : (z == 1) ? wk : (z == 2) ? wv : wo;
  __nv_bfloat16* O = g_wt + ((size_t)z << 20);
  const int n0 = blockIdx.x * 32, k0 = blockIdx.y * 32;
  const int tx = threadIdx.x, ty = threadIdx.y;
#pragma unroll
  for (int r = 0; r < 32; r += 8)
    t[ty + r][tx] = W[(size_t)(k0 + ty + r) * 1024 + n0 + tx];
  __syncthreads();
#pragma unroll
  for (int r = 0; r < 32; r += 8)
    O[(size_t)(n0 + ty + r) * 1024 + k0 + tx] = __float2bfloat16_rn(t[tx][ty + r]);
}

// ============================================================
// bf16 mma.sync GEMM (as R7; Q output pre-scaled by QSC)
// ============================================================
#define GEMM_SMEM 73728
__global__ __launch_bounds__(256) void gemm_tc_kernel(const float* __restrict__ resid,
                                                      int mode) {
  extern __shared__ uint32_t dsm[];
  const int tid = threadIdx.x, lane = tid & 31, wid = tid >> 5;
  const int qr = lane >> 2, qq = lane & 3;
  const int wm = wid & 3, wn = wid >> 2;
  const int z = blockIdx.z;
  const __nv_bfloat16* A = (mode == 0) ? (g_xt + (size_t)z * 4194304) : g_ctx;
  const __nv_bfloat16* Wt = g_wt + ((size_t)(mode == 0 ? z : 3) << 20);
  const int m0 = blockIdx.y * 128, n0 = blockIdx.x * 128;
  const uint32_t sbase = smem_u32(dsm);

  float acc[2][8][4];
#pragma unroll
  for (int i = 0; i < 2; i++)
#pragma unroll
    for (int j = 0; j < 8; j++)
#pragma unroll
      for (int q = 0; q < 4; q++) acc[i][j][q] = 0.f;

#define GEMM_ISSUE(st, kc) do {                                                \
    uint32_t _b = sbase + (st) * 36864;                                        \
    _Pragma("unroll")                                                          \
    for (int t = 0; t < 4; ++t) {                                              \
      int idx = tid + t * 256;                                                 \
      int row = idx >> 3, c = idx & 7;                                         \
      cp16(_b + row * 144 + c * 16, A + (size_t)(m0 + row) * 1024 + (kc) + c * 8);   \
      cp16(_b + 18432 + row * 144 + c * 16,                                    \
           Wt + (size_t)(n0 + row) * 1024 + (kc) + c * 8);                     \
    }                                                                          \
    asm volatile("cp.async.commit_group;" ::: "memory");                       \
  } while (0)

  GEMM_ISSUE(0, 0);

  for (int kt = 0; kt < 16; ++kt) {
    const int s = kt & 1;
    if (kt < 15) {
      GEMM_ISSUE(s ^ 1, (kt + 1) * 64);
      asm volatile("cp.async.wait_group 1;" ::: "memory");
    } else {
      asm volatile("cp.async.wait_group 0;" ::: "memory");
    }
    __syncthreads();
    const uint32_t* As = dsm + s * 9216;
    const uint32_t* Bs = As + 4608;
#pragma unroll
    for (int ks = 0; ks < 4; ++ks) {
      const int kw = ks * 8 + qq;
      uint32_t af[2][4];
#pragma unroll
      for (int tm = 0; tm < 2; ++tm) {
        const uint32_t* p = As + (wm * 32 + tm * 16 + qr) * 36 + kw;
        af[tm][0] = p[0]; af[tm][1] = p[288]; af[tm][2] = p[4]; af[tm][3] = p[292];
      }
#pragma unroll
      for (int tn = 0; tn < 8; ++tn) {
        const uint32_t* p = Bs + (wn * 64 + tn * 8 + qr) * 36 + kw;
        uint32_t bf[2] = {p[0], p[4]};
        mma16(acc[0][tn], af[0], bf);
        mma16(acc[1][tn], af[1], bf);
      }
    }
    __syncthreads();
  }

#pragma unroll
  for (int tm = 0; tm < 2; ++tm) {
#pragma unroll
    for (int tn = 0; tn < 8; ++tn) {
      const int m = m0 + wm * 32 + tm * 16 + qr;
      const int n = n0 + wn * 64 + tn * 8 + 2 * qq;
      float* c = acc[tm][tn];
      if (mode == 0) {
        const int b = m >> 11, sq = m & 2047, h = n >> 6, dk = n & 63;
        if (z == 0) {
          uint32_t* O32 = (uint32_t*)g_q;
          size_t wi = (((size_t)(b * 16 + h) * 2048 + sq) << 5) + (dk >> 1);
          O32[wi] = pk2(c[1] * QSC, c[0] * QSC);
          O32[wi + 256] = pk2(c[3] * QSC, c[2] * QSC);
        } else if (z == 1) {
          uint32_t* O32 = (uint32_t*)g_k;
          size_t wi = (((size_t)(b * 16 + h) * 2048 + sq) << 5) + (dk >> 1);
          O32[wi] = pk2(c[1], c[0]);
          O32[wi + 256] = pk2(c[3], c[2]);
        } else {
          __nv_bfloat16* V = g_v + ((size_t)(b * 16 + h) * 64 + dk) * 2048 + sq;
          V[0]    = __float2bfloat16_rn(c[0]);
          V[2048] = __float2bfloat16_rn(c[1]);
          V[8]    = __float2bfloat16_rn(c[2]);
          V[2056] = __float2bfloat16_rn(c[3]);
        }
      } else {
        float2 r0 = *(const float2*)&resid[(size_t)m * 1024 + n];
        float2 r1 = *(const float2*)&resid[(size_t)(m + 8) * 1024 + n];
        *(float2*)&g_pre[(size_t)m * 1024 + n] = make_float2(c[0] + r0.x, c[1] + r0.y);
        *(float2*)&g_pre[(size_t)(m + 8) * 1024 + n] = make_float2(c[2] + r1.x, c[3] + r1.y);
      }
    }
  }
}

// ============================================================
// Flash attention v5 (bf16, exp2-domain softmax, bitmask).
// 128 threads, 4 warps, warp = 16q x 64keys.
// smem: Q 2304w + 2 stages x (K 2304w + V 2304w) = 46080 B
// ============================================================
#define ATT_SMEM 46080
__global__ __launch_bounds__(128, 4) void attn_kernel() {
  extern __shared__ uint32_t sm[];
  const uint32_t sb = smem_u32(sm);

  const int tid = threadIdx.x, lane = tid & 31, w = tid >> 5;
  const int qr = lane >> 2, qq = lane & 3;
  const int qt = blockIdx.x, h = blockIdx.y, b = blockIdx.z;
  const __nv_bfloat16* Qg = g_q + ((size_t)(b * 16 + h) * 2048 + qt * 64) * 64;
  const __nv_bfloat16* Kg = g_k + (size_t)(b * 16 + h) * 2048 * 64;
  const __nv_bfloat16* Vg = g_v + (size_t)(b * 16 + h) * 64 * 2048;

#define KV_ISSUE(kt, st) do {                                                  \
    uint32_t kb = sb + (2304 + (st) * 4608) * 4;                               \
    _Pragma("unroll")                                                          \
    for (int t = 0; t < 4; ++t) {                                              \
      int idx = tid + t * 128;                                                 \
      int row = idx >> 3, c = idx & 7;                                         \
      cp16(kb + row * 144 + c * 16, Kg + (size_t)((kt) * 64 + row) * 64 + c * 8);   \
      cp16(kb + 9216 + row * 144 + c * 16,                                     \
           Vg + (size_t)row * 2048 + (kt) * 64 + c * 8);                       \
    }                                                                          \
    asm volatile("cp.async.commit_group;" ::: "memory");                       \
  } while (0)

  // stage Q + prefetch kt=0 in one group
#pragma unroll
  for (int t = 0; t < 4; ++t) {
    int idx = tid + t * 128;
    int row = idx >> 3, c = idx & 7;
    cp16(sb + row * 144 + c * 16, Qg + row * 64 + c * 8);
  }
  KV_ISSUE(0, 0);
  asm volatile("cp.async.wait_group 0;" ::: "memory");
  __syncthreads();

  const uint32_t* Qp = sm + (w * 16 + qr) * 36 + qq;
  uint32_t qa[4][4];
#pragma unroll
  for (int ks = 0; ks < 4; ++ks) {
    qa[ks][0] = Qp[ks * 8];
    qa[ks][1] = Qp[288 + ks * 8];
    qa[ks][2] = Qp[ks * 8 + 4];
    qa[ks][3] = Qp[288 + ks * 8 + 4];
  }

  float o[8][4];
#pragma unroll
  for (int i = 0; i < 8; i++)
#pragma unroll
    for (int j = 0; j < 4; j++) o[i][j] = 0.f;
  float m0r = -1e30f, m1r = -1e30f, l0r = 0.f, l1r = 0.f;
  const int r0 = w * 16 + qr;
  const int qg0 = qt * 64 + r0;
  const uint32_t* mb0 = g_mb + (((size_t)b * 2048 + qg0) << 6);  // row r0; +512 for r0+8

  for (int kt = 0; kt < 32; ++kt) {
    const int s = kt & 1;
    if (kt < 31) {
      KV_ISSUE(kt + 1, s ^ 1);
      asm volatile("cp.async.wait_group 1;" ::: "memory");
    } else {
      asm volatile("cp.async.wait_group 0;" ::: "memory");
    }
    // mask bits for this tile (independent of smem state)
    uint2 mA = *(const uint2*)&mb0[kt * 2];
    uint2 mB = *(const uint2*)&mb0[512 + kt * 2];
    __syncthreads();

    const uint32_t* Kp = sm + 2304 + s * 4608 + qr * 36 + qq;
    const uint32_t* Vp = Kp + 2304;

    // S = Q K^T   (Q pre-scaled by 1/8*log2e -> scores in log2 domain)
    float sc[8][4];
#pragma unroll
    for (int i = 0; i < 8; i++)
#pragma unroll
      for (int j = 0; j < 4; j++) sc[i][j] = 0.f;
#pragma unroll
    for (int ks = 0; ks < 4; ++ks) {
#pragma unroll
      for (int tn = 0; tn < 8; ++tn) {
        uint32_t bf[2] = {Kp[tn * 288 + ks * 8], Kp[tn * 288 + ks * 8 + 4]};
        mma16(sc[tn], qa[ks], bf);
      }
    }

    // mask via bit tests
#pragma unroll
    for (int tn = 0; tn < 8; ++tn) {
      uint32_t wa = (tn < 4) ? mA.x : mA.y;
      uint32_t wb = (tn < 4) ? mB.x : mB.y;
      const int pos = (tn & 3) * 8 + 2 * qq;
      if ((wa >> pos) & 1)       sc[tn][0] = NEGB;
      if ((wa >> (pos + 1)) & 1) sc[tn][1] = NEGB;
      if ((wb >> pos) & 1)       sc[tn][2] = NEGB;
      if ((wb >> (pos + 1)) & 1) sc[tn][3] = NEGB;
    }

    // warp-local online softmax (exp2 domain)
    float mx0 = -1e30f, mx1 = -1e30f;
#pragma unroll
    for (int tn = 0; tn < 8; ++tn) {
      mx0 = fmaxf(mx0, fmaxf(sc[tn][0], sc[tn][1]));
      mx1 = fmaxf(mx1, fmaxf(sc[tn][2], sc[tn][3]));
    }
    mx0 = fmaxf(mx0, __shfl_xor_sync(0xffffffffu, mx0, 1));
    mx0 = fmaxf(mx0, __shfl_xor_sync(0xffffffffu, mx0, 2));
    mx1 = fmaxf(mx1, __shfl_xor_sync(0xffffffffu, mx1, 1));
    mx1 = fmaxf(mx1, __shfl_xor_sync(0xffffffffu, mx1, 2));
    float mn0 = fmaxf(m0r, mx0), mn1 = fmaxf(m1r, mx1);
    float f0 = ex2(m0r - mn0), f1 = ex2(m1r - mn1);
    m0r = mn0; m1r = mn1;

    float ls0 = 0.f, ls1 = 0.f;
#pragma unroll
    for (int tn = 0; tn < 8; ++tn) {
      sc[tn][0] = ex2(sc[tn][0] - mn0); ls0 += sc[tn][0];
      sc[tn][1] = ex2(sc[tn][1] - mn0); ls0 += sc[tn][1];
      sc[tn][2] = ex2(sc[tn][2] - mn1); ls1 += sc[tn][2];
      sc[tn][3] = ex2(sc[tn][3] - mn1); ls1 += sc[tn][3];
    }
    ls0 += __shfl_xor_sync(0xffffffffu, ls0, 1);
    ls0 += __shfl_xor_sync(0xffffffffu, ls0, 2);
    ls1 += __shfl_xor_sync(0xffffffffu, ls1, 1);
    ls1 += __shfl_xor_sync(0xffffffffu, ls1, 2);
    l0r = l0r * f0 + ls0;
    l1r = l1r * f1 + ls1;
#pragma unroll
    for (int dt = 0; dt < 8; ++dt) {
      o[dt][0] *= f0; o[dt][1] *= f0; o[dt][2] *= f1; o[dt][3] *= f1;
    }

    // PV: A-frag = packed C-frag, B from transposed V tile
#pragma unroll
    for (int ks = 0; ks < 4; ++ks) {
      uint32_t pa[4];
      pa[0] = pk2(sc[2 * ks][1], sc[2 * ks][0]);
      pa[1] = pk2(sc[2 * ks][3], sc[2 * ks][2]);
      pa[2] = pk2(sc[2 * ks + 1][1], sc[2 * ks + 1][0]);
      pa[3] = pk2(sc[2 * ks + 1][3], sc[2 * ks + 1][2]);
#pragma unroll
      for (int dt = 0; dt < 8; ++dt) {
        uint32_t vf[2] = {Vp[dt * 288 + ks * 8], Vp[dt * 288 + ks * 8 + 4]};
        mma16(o[dt], pa, vf);
      }
    }
    __syncthreads();
  }

  // epilogue -> g_ctx bf16 (merged heads)
  const float i0 = 1.f / l0r, i1 = 1.f / l1r;
  uint32_t* C32 = (uint32_t*)g_ctx;
#pragma unroll
  for (int dt = 0; dt < 8; ++dt) {
    int dk = dt * 8 + 2 * qq;
    size_t wi = (((size_t)b * S_ + qt * 64 + r0) << 9) + ((h * 64 + dk) >> 1);
    C32[wi] = pk2(o[dt][1] * i0, o[dt][0] * i0);
    C32[wi + (8 << 9)] = pk2(o[dt][3] * i1, o[dt][2] * i1);
  }
}

// ------------------------------------------------------------
// LayerNorm over D=1024
// ------------------------------------------------------------
__global__ __launch_bounds__(256) void ln_kernel(const float* __restrict__ gamma,
                                                 const float* __restrict__ beta,
                                                 float* __restrict__ out) {
  __shared__ float red[8];
  __shared__ float bc;
  const int row = blockIdx.x, tid = threadIdx.x;
  const float* x = g_pre + (size_t)row * D_;
  float4 v = *(const float4*)&x[tid * 4];

  float s = v.x + v.y + v.z + v.w;
#pragma unroll
  for (int off = 16; off > 0; off >>= 1) s += __shfl_xor_sync(0xffffffffu, s, off);
  if ((tid & 31) == 0) red[tid >> 5] = s;
  __syncthreads();
  if (tid == 0) {
    float t = 0.f;
#pragma unroll
    for (int i = 0; i < 8; i++) t += red[i];
    bc = t * (1.0f / D_);
  }
  __syncthreads();
  float mu = bc;

  float dx = v.x - mu, dy = v.y - mu, dz = v.z - mu, dw = v.w - mu;
  float sq = dx * dx + dy * dy + dz * dz + dw * dw;
#pragma unroll
  for (int off = 16; off > 0; off >>= 1) sq += __shfl_xor_sync(0xffffffffu, sq, off);
  __syncthreads();
  if ((tid & 31) == 0) red[tid >> 5] = sq;
  __syncthreads();
  if (tid == 0) {
    float t = 0.f;
#pragma unroll
    for (int i = 0; i < 8; i++) t += red[i];
    bc = rsqrtf(t * (1.0f / D_) + 1e-5f);
  }
  __syncthreads();
  float inv = bc;

  float4 g = *(const float4*)&gamma[tid * 4];
  float4 be = *(const float4*)&beta[tid * 4];
  *(float4*)&out[(size_t)row * D_ + tid * 4] =
      make_float4(dx * inv * g.x + be.x, dy * inv * g.y + be.y,
                  dz * inv * g.z + be.z, dw * inv * g.w + be.w);
}

// ------------------------------------------------------------
extern "C" void kernel_launch(void* const* d_in, const int* in_sizes, int n_in,
                              void* d_out, int out_size) {
  const float* xq    = (const float*)d_in[0];
  const float* xk    = (const float*)d_in[1];
  const float* xv    = (const float*)d_in[2];
  const int*   mask  = (const int*)  d_in[3];
  const float* wq    = (const float*)d_in[4];
  const float* wk    = (const float*)d_in[5];
  const float* wv    = (const float*)d_in[6];
  const float* wo    = (const float*)d_in[7];
  const float* gamma = (const float*)d_in[8];
  const float* beta  = (const float*)d_in[9];
  float* out = (float*)d_out;

  cudaFuncSetAttribute(gemm_tc_kernel, cudaFuncAttributeMaxDynamicSharedMemorySize, GEMM_SMEM);
  cudaFuncSetAttribute(attn_kernel, cudaFuncAttributeMaxDynamicSharedMemorySize, ATT_SMEM);

  cvt_x_kernel<<<dim3(4096, 3), 256>>>(xq, xk, xv);
  pack_mask_kernel<<<1024, 256>>>(mask);
  transpose_w_kernel<<<dim3(32, 32, 4), dim3(32, 8)>>>(wq, wk, wv, wo);
  gemm_tc_kernel<<<dim3(8, 32, 3), 256, GEMM_SMEM>>>(nullptr, 0);
  attn_kernel<<<dim3(32, 16, 2), 128, ATT_SMEM>>>();
  gemm_tc_kernel<<<dim3(8, 32, 1), 256, GEMM_SMEM>>>(xq, 1);
  ln_kernel<<<M_, 256>>>(gamma, beta, out);
}

// round 9
// speedup vs baseline: 5.7632x; 1.0193x over previous
#include <cuda_runtime.h>
#include <cuda_bf16.h>
#include <cstdint>

#define B_ 2
#define S_ 2048
#define D_ 1024
#define H_ 16
#define DK_ 64
#define M_ (B_*S_)

#define QSC 0.18033688011112042f
#define NEGB (-1.4426950408889634e9f)

// ---- static device scratch ----
__device__ __nv_bfloat16 g_q[4194304];    // [B,H,S,DK]  (pre-scaled by QSC)
__device__ __nv_bfloat16 g_k[4194304];    // [B,H,S,DK]
__device__ __nv_bfloat16 g_v[4194304];    // [B,H,DK,S]  (transposed)
__device__ __nv_bfloat16 g_ctx[4194304];  // [B*S, D]
__device__ __nv_bfloat16 g_wt[4194304];   // W^T x4 [n][k]
__device__ __nv_bfloat16 g_xt[12582912];  // xq/xk/xv bf16
__device__ float g_pre[4194304];          // fp32 pre-LN
__device__ uint32_t g_mb[262144];         // bit-packed mask

// ---- helpers ----
__device__ __forceinline__ uint32_t pk2(float hi, float lo) {
  uint32_t r; asm("cvt.rn.bf16x2.f32 %0, %1, %2;" : "=r"(r) : "f"(hi), "f"(lo));
  return r;
}
__device__ __forceinline__ float ex2(float x) {
  float r; asm("ex2.approx.f32 %0, %1;" : "=f"(r) : "f"(x)); return r;
}
__device__ __forceinline__ uint32_t smem_u32(const void* p) {
  uint32_t a;
  asm("{ .reg .u64 t; cvta.to.shared.u64 t, %1; cvt.u32.u64 %0, t; }" : "=r"(a) : "l"(p));
  return a;
}
__device__ __forceinline__ void cp16(uint32_t d, const void* s) {
  asm volatile("cp.async.cg.shared.global [%0], [%1], 16;" :: "r"(d), "l"(s) : "memory");
}
__device__ __forceinline__ void mma16(float* d, const uint32_t* a, const uint32_t* b) {
  asm volatile(
    "mma.sync.aligned.m16n8k16.row.col.f32.bf16.bf16.f32 "
    "{%0,%1,%2,%3}, {%4,%5,%6,%7}, {%8,%9}, {%0,%1,%2,%3};"
    : "+f"(d[0]), "+f"(d[1]), "+f"(d[2]), "+f"(d[3])
    : "r"(a[0]), "r"(a[1]), "r"(a[2]), "r"(a[3]), "r"(b[0]), "r"(b[1]));
}
__device__ __forceinline__ void ldsm4(uint32_t* r, uint32_t addr) {
  asm volatile("ldmatrix.sync.aligned.m8n8.x4.shared.b16 {%0,%1,%2,%3}, [%4];"
    : "=r"(r[0]), "=r"(r[1]), "=r"(r[2]), "=r"(r[3]) : "r"(addr));
}

// ============================================================
// Prepass: fp32 -> bf16
// ============================================================
__global__ __launch_bounds__(256) void cvt_x_kernel(
    const float* __restrict__ xq, const float* __restrict__ xk,
    const float* __restrict__ xv) {
  const float* x = (blockIdx.y == 0) ? xq : (blockIdx.y == 1) ? xk : xv;
  uint32_t* o32 = (uint32_t*)(g_xt + (size_t)blockIdx.y * 4194304);
  size_t i = ((size_t)blockIdx.x * 256 + threadIdx.x) * 4;
  float4 v = *(const float4*)&x[i];
  o32[(i >> 1)]     = pk2(v.y, v.x);
  o32[(i >> 1) + 1] = pk2(v.w, v.z);
}

// ============================================================
// Prepass: bit-pack mask
// ============================================================
__global__ __launch_bounds__(256) void pack_mask_kernel(const int* __restrict__ m) {
  size_t w = (size_t)blockIdx.x * 256 + threadIdx.x;
  const int4* p = (const int4*)(m + w * 32);
  uint32_t bits = 0;
#pragma unroll
  for (int i = 0; i < 8; ++i) {
    int4 v = p[i];
    bits |= (v.x ? 1u : 0u) << (4 * i)
          | (v.y ? 1u : 0u) << (4 * i + 1)
          | (v.z ? 1u : 0u) << (4 * i + 2)
          | (v.w ? 1u : 0u) << (4 * i + 3);
  }
  g_mb[w] = bits;
}

// ============================================================
// Weight transpose + bf16
// ============================================================
__global__ __launch_bounds__(256) void transpose_w_kernel(
    const float* __restrict__ wq, const float* __restrict__ wk,
    const float* __restrict__ wv, const float* __restrict__ wo) {
  __shared__ float t[32][33];
  const int z = blockIdx.z;
  const float* W = (z == 0) ? wq : (z == 1) ? wk : (z == 2) ? wv : wo;
  __nv_bfloat16* O = g_wt + ((size_t)z << 20);
  const int n0 = blockIdx.x * 32, k0 = blockIdx.y * 32;
  const int tx = threadIdx.x, ty = threadIdx.y;
#pragma unroll
  for (int r = 0; r < 32; r += 8)
    t[ty + r][tx] = W[(size_t)(k0 + ty + r) * 1024 + n0 + tx];
  __syncthreads();
#pragma unroll
  for (int r = 0; r < 32; r += 8)
    O[(size_t)(n0 + ty + r) * 1024 + k0 + tx] = __float2bfloat16_rn(t[tx][ty + r]);
}

// ============================================================
// bf16 mma.sync GEMM with ldmatrix fragments
// ============================================================
#define GEMM_SMEM 73728
__global__ __launch_bounds__(256) void gemm_tc_kernel(const float* __restrict__ resid,
                                                      int mode) {
  extern __shared__ uint32_t dsm[];
  const int tid = threadIdx.x, lane = tid & 31, wid = tid >> 5;
  const int qr = lane >> 2, qq = lane & 3;
  const int wm = wid & 3, wn = wid >> 2;
  const int z = blockIdx.z;
  const __nv_bfloat16* A = (mode == 0) ? (g_xt + (size_t)z * 4194304) : g_ctx;
  const __nv_bfloat16* Wt = g_wt + ((size_t)(mode == 0 ? z : 3) << 20);
  const int m0 = blockIdx.y * 128, n0 = blockIdx.x * 128;
  const uint32_t sbase = smem_u32(dsm);

  // ldmatrix lane geometry
  const int lrow = (lane & 7) + ((lane >> 3) & 1) * 8;
  const int lcol = (lane >> 4) * 4;  // words

  float acc[2][8][4];
#pragma unroll
  for (int i = 0; i < 2; i++)
#pragma unroll
    for (int j = 0; j < 8; j++)
#pragma unroll
      for (int q = 0; q < 4; q++) acc[i][j][q] = 0.f;

#define GEMM_ISSUE(st, kc) do {                                                \
    uint32_t _b = sbase + (st) * 36864;                                        \
    _Pragma("unroll")                                                          \
    for (int t = 0; t < 4; ++t) {                                              \
      int idx = tid + t * 256;                                                 \
      int row = idx >> 3, c = idx & 7;                                         \
      cp16(_b + row * 144 + c * 16, A + (size_t)(m0 + row) * 1024 + (kc) + c * 8);   \
      cp16(_b + 18432 + row * 144 + c * 16,                                    \
           Wt + (size_t)(n0 + row) * 1024 + (kc) + c * 8);                     \
    }                                                                          \
    asm volatile("cp.async.commit_group;" ::: "memory");                       \
  } while (0)

  GEMM_ISSUE(0, 0);

  const uint32_t aoff = (uint32_t)((wm * 32 + lrow) * 36 + lcol) * 4;
  const uint32_t boff = 18432u + (uint32_t)((wn * 64 + lrow) * 36 + lcol) * 4;

  for (int kt = 0; kt < 16; ++kt) {
    const int s = kt & 1;
    if (kt < 15) {
      GEMM_ISSUE(s ^ 1, (kt + 1) * 64);
      asm volatile("cp.async.wait_group 1;" ::: "memory");
    } else {
      asm volatile("cp.async.wait_group 0;" ::: "memory");
    }
    __syncthreads();
    const uint32_t aaddr = sbase + s * 36864 + aoff;
    const uint32_t baddr = sbase + s * 36864 + boff;
#pragma unroll
    for (int ks = 0; ks < 4; ++ks) {
      uint32_t af[2][4];
      ldsm4(af[0], aaddr + ks * 32);
      ldsm4(af[1], aaddr + 16 * 144 + ks * 32);
#pragma unroll
      for (int tg = 0; tg < 4; ++tg) {
        uint32_t bb[4];
        ldsm4(bb, baddr + tg * (16 * 144) + ks * 32);
        uint32_t bf0[2] = {bb[0], bb[2]};
        uint32_t bf1[2] = {bb[1], bb[3]};
        mma16(acc[0][2 * tg], af[0], bf0);
        mma16(acc[1][2 * tg], af[1], bf0);
        mma16(acc[0][2 * tg + 1], af[0], bf1);
        mma16(acc[1][2 * tg + 1], af[1], bf1);
      }
    }
    __syncthreads();
  }

#pragma unroll
  for (int tm = 0; tm < 2; ++tm) {
#pragma unroll
    for (int tn = 0; tn < 8; ++tn) {
      const int m = m0 + wm * 32 + tm * 16 + qr;
      const int n = n0 + wn * 64 + tn * 8 + 2 * qq;
      float* c = acc[tm][tn];
      if (mode == 0) {
        const int b = m >> 11, sq = m & 2047, h = n >> 6, dk = n & 63;
        if (z == 0) {
          uint32_t* O32 = (uint32_t*)g_q;
          size_t wi = (((size_t)(b * 16 + h) * 2048 + sq) << 5) + (dk >> 1);
          O32[wi] = pk2(c[1] * QSC, c[0] * QSC);
          O32[wi + 256] = pk2(c[3] * QSC, c[2] * QSC);
        } else if (z == 1) {
          uint32_t* O32 = (uint32_t*)g_k;
          size_t wi = (((size_t)(b * 16 + h) * 2048 + sq) << 5) + (dk >> 1);
          O32[wi] = pk2(c[1], c[0]);
          O32[wi + 256] = pk2(c[3], c[2]);
        } else {
          __nv_bfloat16* V = g_v + ((size_t)(b * 16 + h) * 64 + dk) * 2048 + sq;
          V[0]    = __float2bfloat16_rn(c[0]);
          V[2048] = __float2bfloat16_rn(c[1]);
          V[8]    = __float2bfloat16_rn(c[2]);
          V[2056] = __float2bfloat16_rn(c[3]);
        }
      } else {
        float2 r0 = *(const float2*)&resid[(size_t)m * 1024 + n];
        float2 r1 = *(const float2*)&resid[(size_t)(m + 8) * 1024 + n];
        *(float2*)&g_pre[(size_t)m * 1024 + n] = make_float2(c[0] + r0.x, c[1] + r0.y);
        *(float2*)&g_pre[(size_t)(m + 8) * 1024 + n] = make_float2(c[2] + r1.x, c[3] + r1.y);
      }
    }
  }
}

// ============================================================
// Flash attention v6 (bf16, exp2 softmax, bitmask, ldmatrix)
// smem: Q 2304w + 2 stages x (K 2304w + V 2304w) = 46080 B
// ============================================================
#define ATT_SMEM 46080
__global__ __launch_bounds__(128, 4) void attn_kernel() {
  extern __shared__ uint32_t sm[];
  const uint32_t sb = smem_u32(sm);

  const int tid = threadIdx.x, lane = tid & 31, w = tid >> 5;
  const int qr = lane >> 2, qq = lane & 3;
  const int qt = blockIdx.x, h = blockIdx.y, b = blockIdx.z;
  const __nv_bfloat16* Qg = g_q + ((size_t)(b * 16 + h) * 2048 + qt * 64) * 64;
  const __nv_bfloat16* Kg = g_k + (size_t)(b * 16 + h) * 2048 * 64;
  const __nv_bfloat16* Vg = g_v + (size_t)(b * 16 + h) * 64 * 2048;

  const int lrow = (lane & 7) + ((lane >> 3) & 1) * 8;
  const int lcol = (lane >> 4) * 4;

#define KV_ISSUE(kt, st) do {                                                  \
    uint32_t kb = sb + (2304 + (st) * 4608) * 4;                               \
    _Pragma("unroll")                                                          \
    for (int t = 0; t < 4; ++t) {                                              \
      int idx = tid + t * 128;                                                 \
      int row = idx >> 3, c = idx & 7;                                         \
      cp16(kb + row * 144 + c * 16, Kg + (size_t)((kt) * 64 + row) * 64 + c * 8);   \
      cp16(kb + 9216 + row * 144 + c * 16,                                     \
           Vg + (size_t)row * 2048 + (kt) * 64 + c * 8);                       \
    }                                                                          \
    asm volatile("cp.async.commit_group;" ::: "memory");                       \
  } while (0)

  // stage Q + prefetch kt=0
#pragma unroll
  for (int t = 0; t < 4; ++t) {
    int idx = tid + t * 128;
    int row = idx >> 3, c = idx & 7;
    cp16(sb + row * 144 + c * 16, Qg + row * 64 + c * 8);
  }
  KV_ISSUE(0, 0);
  asm volatile("cp.async.wait_group 0;" ::: "memory");
  __syncthreads();

  // Q A-fragments via ldmatrix
  const uint32_t qaddr = sb + (uint32_t)((w * 16 + lrow) * 36 + lcol) * 4;
  uint32_t qa[4][4];
#pragma unroll
  for (int ks = 0; ks < 4; ++ks) ldsm4(qa[ks], qaddr + ks * 32);

  float o[8][4];
#pragma unroll
  for (int i = 0; i < 8; i++)
#pragma unroll
    for (int j = 0; j < 4; j++) o[i][j] = 0.f;
  float m0r = -1e30f, m1r = -1e30f, l0r = 0.f, l1r = 0.f;
  const int r0 = w * 16 + qr;
  const int qg0 = qt * 64 + r0;
  const uint32_t* mb0 = g_mb + (((size_t)b * 2048 + qg0) << 6);
  const uint32_t fragoff = (uint32_t)(lrow * 36 + lcol) * 4;

  for (int kt = 0; kt < 32; ++kt) {
    const int s = kt & 1;
    if (kt < 31) {
      KV_ISSUE(kt + 1, s ^ 1);
      asm volatile("cp.async.wait_group 1;" ::: "memory");
    } else {
      asm volatile("cp.async.wait_group 0;" ::: "memory");
    }
    uint2 mA = *(const uint2*)&mb0[kt * 2];
    uint2 mB = *(const uint2*)&mb0[512 + kt * 2];
    __syncthreads();

    const uint32_t kaddr = sb + (2304 + s * 4608) * 4 + fragoff;
    const uint32_t vaddr = kaddr + 9216;

    // S = Q K^T
    float sc[8][4];
#pragma unroll
    for (int i = 0; i < 8; i++)
#pragma unroll
      for (int j = 0; j < 4; j++) sc[i][j] = 0.f;
#pragma unroll
    for (int ks = 0; ks < 4; ++ks) {
#pragma unroll
      for (int tg = 0; tg < 4; ++tg) {
        uint32_t bb[4];
        ldsm4(bb, kaddr + tg * (16 * 144) + ks * 32);
        uint32_t bf0[2] = {bb[0], bb[2]};
        uint32_t bf1[2] = {bb[1], bb[3]};
        mma16(sc[2 * tg], qa[ks], bf0);
        mma16(sc[2 * tg + 1], qa[ks], bf1);
      }
    }

    // mask via bit tests
#pragma unroll
    for (int tn = 0; tn < 8; ++tn) {
      uint32_t wa = (tn < 4) ? mA.x : mA.y;
      uint32_t wb = (tn < 4) ? mB.x : mB.y;
      const int pos = (tn & 3) * 8 + 2 * qq;
      if ((wa >> pos) & 1)       sc[tn][0] = NEGB;
      if ((wa >> (pos + 1)) & 1) sc[tn][1] = NEGB;
      if ((wb >> pos) & 1)       sc[tn][2] = NEGB;
      if ((wb >> (pos + 1)) & 1) sc[tn][3] = NEGB;
    }

    // warp-local online softmax (exp2 domain)
    float mx0 = -1e30f, mx1 = -1e30f;
#pragma unroll
    for (int tn = 0; tn < 8; ++tn) {
      mx0 = fmaxf(mx0, fmaxf(sc[tn][0], sc[tn][1]));
      mx1 = fmaxf(mx1, fmaxf(sc[tn][2], sc[tn][3]));
    }
    mx0 = fmaxf(mx0, __shfl_xor_sync(0xffffffffu, mx0, 1));
    mx0 = fmaxf(mx0, __shfl_xor_sync(0xffffffffu, mx0, 2));
    mx1 = fmaxf(mx1, __shfl_xor_sync(0xffffffffu, mx1, 1));
    mx1 = fmaxf(mx1, __shfl_xor_sync(0xffffffffu, mx1, 2));
    float mn0 = fmaxf(m0r, mx0), mn1 = fmaxf(m1r, mx1);
    float f0 = ex2(m0r - mn0), f1 = ex2(m1r - mn1);
    m0r = mn0; m1r = mn1;

    float ls0 = 0.f, ls1 = 0.f;
#pragma unroll
    for (int tn = 0; tn < 8; ++tn) {
      sc[tn][0] = ex2(sc[tn][0] - mn0); ls0 += sc[tn][0];
      sc[tn][1] = ex2(sc[tn][1] - mn0); ls0 += sc[tn][1];
      sc[tn][2] = ex2(sc[tn][2] - mn1); ls1 += sc[tn][2];
      sc[tn][3] = ex2(sc[tn][3] - mn1); ls1 += sc[tn][3];
    }
    ls0 += __shfl_xor_sync(0xffffffffu, ls0, 1);
    ls0 += __shfl_xor_sync(0xffffffffu, ls0, 2);
    ls1 += __shfl_xor_sync(0xffffffffu, ls1, 1);
    ls1 += __shfl_xor_sync(0xffffffffu, ls1, 2);
    l0r = l0r * f0 + ls0;
    l1r = l1r * f1 + ls1;
#pragma unroll
    for (int dt = 0; dt < 8; ++dt) {
      o[dt][0] *= f0; o[dt][1] *= f0; o[dt][2] *= f1; o[dt][3] *= f1;
    }

    // PV: A-frag = packed C-frag; V B-frags via ldmatrix
#pragma unroll
    for (int ks = 0; ks < 4; ++ks) {
      uint32_t pa[4];
      pa[0] = pk2(sc[2 * ks][1], sc[2 * ks][0]);
      pa[1] = pk2(sc[2 * ks][3], sc[2 * ks][2]);
      pa[2] = pk2(sc[2 * ks + 1][1], sc[2 * ks + 1][0]);
      pa[3] = pk2(sc[2 * ks + 1][3], sc[2 * ks + 1][2]);
#pragma unroll
      for (int dg = 0; dg < 4; ++dg) {
        uint32_t bb[4];
        ldsm4(bb, vaddr + dg * (16 * 144) + ks * 32);
        uint32_t bf0[2] = {bb[0], bb[2]};
        uint32_t bf1[2] = {bb[1], bb[3]};
        mma16(o[2 * dg], pa, bf0);
        mma16(o[2 * dg + 1], pa, bf1);
      }
    }
    __syncthreads();
  }

  // epilogue -> g_ctx bf16 (merged heads)
  const float i0 = 1.f / l0r, i1 = 1.f / l1r;
  uint32_t* C32 = (uint32_t*)g_ctx;
#pragma unroll
  for (int dt = 0; dt < 8; ++dt) {
    int dk = dt * 8 + 2 * qq;
    size_t wi = (((size_t)b * S_ + qt * 64 + r0) << 9) + ((h * 64 + dk) >> 1);
    C32[wi] = pk2(o[dt][1] * i0, o[dt][0] * i0);
    C32[wi + (8 << 9)] = pk2(o[dt][3] * i1, o[dt][2] * i1);
  }
}

// ------------------------------------------------------------
// LayerNorm over D=1024
// ------------------------------------------------------------
__global__ __launch_bounds__(256) void ln_kernel(const float* __restrict__ gamma,
                                                 const float* __restrict__ beta,
                                                 float* __restrict__ out) {
  __shared__ float red[8];
  __shared__ float bc;
  const int row = blockIdx.x, tid = threadIdx.x;
  const float* x = g_pre + (size_t)row * D_;
  float4 v = *(const float4*)&x[tid * 4];

  float s = v.x + v.y + v.z + v.w;
#pragma unroll
  for (int off = 16; off > 0; off >>= 1) s += __shfl_xor_sync(0xffffffffu, s, off);
  if ((tid & 31) == 0) red[tid >> 5] = s;
  __syncthreads();
  if (tid == 0) {
    float t = 0.f;
#pragma unroll
    for (int i = 0; i < 8; i++) t += red[i];
    bc = t * (1.0f / D_);
  }
  __syncthreads();
  float mu = bc;

  float dx = v.x - mu, dy = v.y - mu, dz = v.z - mu, dw = v.w - mu;
  float sq = dx * dx + dy * dy + dz * dz + dw * dw;
#pragma unroll
  for (int off = 16; off > 0; off >>= 1) sq += __shfl_xor_sync(0xffffffffu, sq, off);
  __syncthreads();
  if ((tid & 31) == 0) red[tid >> 5] = sq;
  __syncthreads();
  if (tid == 0) {
    float t = 0.f;
#pragma unroll
    for (int i = 0; i < 8; i++) t += red[i];
    bc = rsqrtf(t * (1.0f / D_) + 1e-5f);
  }
  __syncthreads();
  float inv = bc;

  float4 g = *(const float4*)&gamma[tid * 4];
  float4 be = *(const float4*)&beta[tid * 4];
  *(float4*)&out[(size_t)row * D_ + tid * 4] =
      make_float4(dx * inv * g.x + be.x, dy * inv * g.y + be.y,
                  dz * inv * g.z + be.z, dw * inv * g.w + be.w);
}

// ------------------------------------------------------------
extern "C" void kernel_launch(void* const* d_in, const int* in_sizes, int n_in,
                              void* d_out, int out_size) {
  const float* xq    = (const float*)d_in[0];
  const float* xk    = (const float*)d_in[1];
  const float* xv    = (const float*)d_in[2];
  const int*   mask  = (const int*)  d_in[3];
  const float* wq    = (const float*)d_in[4];
  const float* wk    = (const float*)d_in[5];
  const float* wv    = (const float*)d_in[6];
  const float* wo    = (const float*)d_in[7];
  const float* gamma = (const float*)d_in[8];
  const float* beta  = (const float*)d_in[9];
  float* out = (float*)d_out;

  cudaFuncSetAttribute(gemm_tc_kernel, cudaFuncAttributeMaxDynamicSharedMemorySize, GEMM_SMEM);
  cudaFuncSetAttribute(attn_kernel, cudaFuncAttributeMaxDynamicSharedMemorySize, ATT_SMEM);

  cvt_x_kernel<<<dim3(4096, 3), 256>>>(xq, xk, xv);
  pack_mask_kernel<<<1024, 256>>>(mask);
  transpose_w_kernel<<<dim3(32, 32, 4), dim3(32, 8)>>>(wq, wk, wv, wo);
  gemm_tc_kernel<<<dim3(8, 32, 3), 256, GEMM_SMEM>>>(nullptr, 0);
  attn_kernel<<<dim3(32, 16, 2), 128, ATT_SMEM>>>();
  gemm_tc_kernel<<<dim3(8, 32, 1), 256, GEMM_SMEM>>>(xq, 1);
  ln_kernel<<<M_, 256>>>(gamma, beta, out);
}